// round 9
// baseline (speedup 1.0000x reference)
#include <cuda_runtime.h>
#include <cstdint>

// ---------------------------------------------------------------------------
// GNBlock: h = BN(PReLU(segment_sum(relu(x[src]@W1+b1)@W2+b2, dst) + x@W_root + b_root))
// N=50000, E=800000, C_IN=64, C_HID=128, C_OUT=64
//
// msg = MLP(x[src]) per node (persistent kernel). Gather aggregation over a
// dst-sorted CSR (single-block scan). PReLU+BN fully fused into the gather
// kernel via a grid-wide spin barrier (acc rows stay in registers).
// 6 launches total.
// ---------------------------------------------------------------------------

#define N_MAX 50000
#define E_MAX 800000
#define C_IN 64
#define C_HID 128
#define C_OUT 64
#define TILE_N 128
#define MT 512
#define NT 256
#define AGG_BLOCKS 592
#define MAX_NPG 6  // ceil(N_MAX / (AGG_BLOCKS*16)) = 6

__device__ __align__(16) float g_h[N_MAX * C_OUT];    // root transform
__device__ __align__(16) float g_msg[N_MAX * C_OUT];  // per-node messages
__device__ float g_stats[2 * C_OUT];
__device__ int g_idx64;
__device__ int g_done;
__device__ int g_cnt[N_MAX];
__device__ int g_off[N_MAX + 1];
__device__ int g_cursor[N_MAX];
__device__ int g_esrc[E_MAX];  // src list, CSR-ordered by dst

// ---- f32x2 packed helpers ---------------------------------------------------
__device__ __forceinline__ unsigned long long pack2(float v) {
    unsigned long long r;
    unsigned int u = __float_as_uint(v);
    asm("mov.b64 %0, {%1, %2};" : "=l"(r) : "r"(u), "r"(u));
    return r;
}
__device__ __forceinline__ unsigned long long fma2(unsigned long long a,
                                                   unsigned long long b,
                                                   unsigned long long c) {
    unsigned long long d;
    asm("fma.rn.f32x2 %0, %1, %2, %3;" : "=l"(d) : "l"(a), "l"(b), "l"(c));
    return d;
}
__device__ __forceinline__ float2 unpack2(unsigned long long v) {
    unsigned int lo, hi;
    asm("mov.b64 {%0, %1}, %2;" : "=r"(lo), "=r"(hi) : "l"(v));
    float2 f;
    f.x = __uint_as_float(lo);
    f.y = __uint_as_float(hi);
    return f;
}

// ---------------------------------------------------------------------------
// K0: zero g_cnt/g_stats/g_done + detect index width
// ---------------------------------------------------------------------------
__global__ void setup_kernel(const void* __restrict__ ei, int N) {
    int gid = blockIdx.x * blockDim.x + threadIdx.x;
    int stride = gridDim.x * blockDim.x;
    for (int i = gid; i < N; i += stride) g_cnt[i] = 0;
    if (gid < 128) g_stats[gid] = 0.f;
    if (gid == 128) g_done = 0;
    if (blockIdx.x == 0 && threadIdx.x < 32) {
        const long long* p = (const long long*)ei;
        long long v = p[threadIdx.x];
        unsigned ok = __ballot_sync(0xffffffffu, v >= 0 && v < (long long)N);
        if (threadIdx.x == 0) g_idx64 = (ok == 0xffffffffu) ? 1 : 0;
    }
}

// ---------------------------------------------------------------------------
// K1: histogram of dst (loads dst column only)
// ---------------------------------------------------------------------------
__global__ void hist_kernel(const void* __restrict__ ei, int E) {
    int e = blockIdx.x * blockDim.x + threadIdx.x;
    if (e >= E) return;
    int d;
    if (g_idx64) d = (int)__ldg(&((const long long*)ei)[E + e]);
    else d = __ldg(&((const int*)ei)[E + e]);
    atomicAdd(&g_cnt[d], 1);
}

// ---------------------------------------------------------------------------
// K2: SINGLE-BLOCK exclusive scan (1024 threads, each owns a serial chunk).
// ---------------------------------------------------------------------------
__global__ __launch_bounds__(1024) void scan_kernel(int N) {
    const int T = 1024;
    int t = threadIdx.x;
    int lane = t & 31, wid = t >> 5;
    int chunk = (N + T - 1) / T;
    int beg = t * chunk;
    int end = beg + chunk;
    if (beg > N) beg = N;
    if (end > N) end = N;

    int sum = 0;
    for (int i = beg; i < end; i++) sum += g_cnt[i];

    // inclusive shfl scan within warp
    int inc = sum;
#pragma unroll
    for (int o = 1; o < 32; o <<= 1) {
        int u = __shfl_up_sync(0xffffffffu, inc, o);
        if (lane >= o) inc += u;
    }
    __shared__ int wsum[32];
    if (lane == 31) wsum[wid] = inc;
    __syncthreads();
    if (wid == 0) {
        int v = wsum[lane];
        int wi = v;
#pragma unroll
        for (int o = 1; o < 32; o <<= 1) {
            int u = __shfl_up_sync(0xffffffffu, wi, o);
            if (lane >= o) wi += u;
        }
        wsum[lane] = wi - v;  // exclusive warp prefix
    }
    __syncthreads();
    int run = wsum[wid] + inc - sum;  // exclusive prefix for this thread's chunk
    for (int i = beg; i < end; i++) {
        int c = g_cnt[i];
        g_off[i] = run;
        g_cursor[i] = run;
        run += c;
    }
    if (end == N) g_off[N] = run;  // all threads with end==N write the same total
}

// ---------------------------------------------------------------------------
// K3: bucket edges by dst: g_esrc[pos] = src
// ---------------------------------------------------------------------------
__global__ void reorder_kernel(const void* __restrict__ ei, int E) {
    int e = blockIdx.x * blockDim.x + threadIdx.x;
    if (e >= E) return;
    int s, d;
    if (g_idx64) {
        const long long* p = (const long long*)ei;
        s = (int)__ldg(&p[e]);
        d = (int)__ldg(&p[E + e]);
    } else {
        const int* p = (const int*)ei;
        s = __ldg(&p[e]);
        d = __ldg(&p[E + e]);
    }
    int pos = atomicAdd(&g_cursor[d], 1);
    g_esrc[pos] = s;
}

// ---------------------------------------------------------------------------
// K4: PERSISTENT fused per-node kernel (weights staged once per block):
//   msg[n] = relu(x[n]@W1 + b1) @ W2 + b2  -> g_msg
//   h[n]   = x[n]@W_root + b_root          -> g_h
// ---------------------------------------------------------------------------
#define SX_PITCH 68
#define SH_PITCH 132
#define SMEM_FLOATS (8192 + 8192 + 4096 + TILE_N * SX_PITCH + TILE_N * SH_PITCH + 256)
#define SMEM_BYTES (SMEM_FLOATS * 4)

__global__ __launch_bounds__(MT) void msg_kernel(
    const float* __restrict__ x, const float* __restrict__ W1,
    const float* __restrict__ b1, const float* __restrict__ W2,
    const float* __restrict__ b2, const float* __restrict__ Wr,
    const float* __restrict__ br, int N, int numTiles) {
    extern __shared__ float sm[];
    float* sW1 = sm;                      // 64 x 128
    float* sW2 = sW1 + 64 * 128;          // 128 x 64
    float* sWr = sW2 + 128 * 64;          // 64 x 64
    float* sX = sWr + 64 * 64;            // 128 x 68 (padded)
    float* sH = sX + TILE_N * SX_PITCH;   // 128 x 132 (padded)
    float* sb1 = sH + TILE_N * SH_PITCH;  // 128
    float* sb2 = sb1 + 128;               // 64
    float* sbr = sb2 + 64;                // 64

    const int tid = threadIdx.x;

    for (int i = tid; i < 2048; i += MT)
        reinterpret_cast<float4*>(sW1)[i] = reinterpret_cast<const float4*>(W1)[i];
    for (int i = tid; i < 2048; i += MT)
        reinterpret_cast<float4*>(sW2)[i] = reinterpret_cast<const float4*>(W2)[i];
    for (int i = tid; i < 1024; i += MT)
        reinterpret_cast<float4*>(sWr)[i] = reinterpret_cast<const float4*>(Wr)[i];
    if (tid < 128) sb1[tid] = b1[tid];
    else if (tid < 192) sb2[tid - 128] = b2[tid - 128];
    else if (tid < 256) sbr[tid - 192] = br[tid - 192];

    const int hg = tid & 15;
    const int rg = tid >> 4;
    const int hb = hg * 8;
    const int kb = hg * 4;
    const int rb = rg * 4;

    for (int tile = blockIdx.x; tile < numTiles; tile += gridDim.x) {
        const int n0 = tile * TILE_N;
        __syncthreads();  // prior tile's sH readers done; weights staged

        for (int i = tid; i < TILE_N * 16; i += MT) {
            int r = i >> 4, q = i & 15;
            int n = n0 + r;
            if (n >= N) n = N - 1;
            float4 v = reinterpret_cast<const float4*>(x + (long long)n * C_IN)[q];
            *reinterpret_cast<float4*>(&sX[r * SX_PITCH + q * 4]) = v;
        }
        __syncthreads();

        // ---- GEMM1: sH = relu(sX @ W1 + b1) ----
        {
            unsigned long long acc[4][4];
#pragma unroll
            for (int e = 0; e < 4; e++)
#pragma unroll
                for (int p = 0; p < 4; p++) acc[e][p] = 0ULL;

#pragma unroll 8
            for (int k = 0; k < C_IN; k += 2) {
                ulonglong2 wa0 = *reinterpret_cast<const ulonglong2*>(&sW1[k * C_HID + hb]);
                ulonglong2 wa1 =
                    *reinterpret_cast<const ulonglong2*>(&sW1[k * C_HID + hb + 4]);
                ulonglong2 wb0 =
                    *reinterpret_cast<const ulonglong2*>(&sW1[(k + 1) * C_HID + hb]);
                ulonglong2 wb1 =
                    *reinterpret_cast<const ulonglong2*>(&sW1[(k + 1) * C_HID + hb + 4]);
#pragma unroll
                for (int e = 0; e < 4; e++) {
                    float2 xv = *reinterpret_cast<const float2*>(&sX[(rb + e) * SX_PITCH + k]);
                    unsigned long long x0 = pack2(xv.x), x1 = pack2(xv.y);
                    acc[e][0] = fma2(x0, wa0.x, acc[e][0]);
                    acc[e][1] = fma2(x0, wa0.y, acc[e][1]);
                    acc[e][2] = fma2(x0, wa1.x, acc[e][2]);
                    acc[e][3] = fma2(x0, wa1.y, acc[e][3]);
                    acc[e][0] = fma2(x1, wb0.x, acc[e][0]);
                    acc[e][1] = fma2(x1, wb0.y, acc[e][1]);
                    acc[e][2] = fma2(x1, wb1.x, acc[e][2]);
                    acc[e][3] = fma2(x1, wb1.y, acc[e][3]);
                }
            }
#pragma unroll
            for (int e = 0; e < 4; e++) {
#pragma unroll
                for (int p = 0; p < 4; p++) {
                    float2 v = unpack2(acc[e][p]);
                    v.x = fmaxf(v.x + sb1[hb + 2 * p], 0.f);
                    v.y = fmaxf(v.y + sb1[hb + 2 * p + 1], 0.f);
                    *reinterpret_cast<float2*>(&sH[(rb + e) * SH_PITCH + hb + 2 * p]) = v;
                }
            }
        }

        // ---- GEMM3: g_h = sX @ W_root + b_root ----
        {
            unsigned long long a3[4][2];
#pragma unroll
            for (int e = 0; e < 4; e++) { a3[e][0] = 0ULL; a3[e][1] = 0ULL; }

#pragma unroll 8
            for (int k = 0; k < C_IN; k += 2) {
                ulonglong2 wa = *reinterpret_cast<const ulonglong2*>(&sWr[k * C_OUT + kb]);
                ulonglong2 wb =
                    *reinterpret_cast<const ulonglong2*>(&sWr[(k + 1) * C_OUT + kb]);
#pragma unroll
                for (int e = 0; e < 4; e++) {
                    float2 xv = *reinterpret_cast<const float2*>(&sX[(rb + e) * SX_PITCH + k]);
                    unsigned long long x0 = pack2(xv.x), x1 = pack2(xv.y);
                    a3[e][0] = fma2(x0, wa.x, a3[e][0]);
                    a3[e][1] = fma2(x0, wa.y, a3[e][1]);
                    a3[e][0] = fma2(x1, wb.x, a3[e][0]);
                    a3[e][1] = fma2(x1, wb.y, a3[e][1]);
                }
            }
            float c0 = sbr[kb], c1 = sbr[kb + 1], c2 = sbr[kb + 2], c3 = sbr[kb + 3];
#pragma unroll
            for (int e = 0; e < 4; e++) {
                int n = n0 + rb + e;
                if (n >= N) continue;
                float2 v0 = unpack2(a3[e][0]);
                float2 v1 = unpack2(a3[e][1]);
                float4 r;
                r.x = v0.x + c0; r.y = v0.y + c1; r.z = v1.x + c2; r.w = v1.y + c3;
                *reinterpret_cast<float4*>(&g_h[(long long)n * C_OUT + kb]) = r;
            }
        }
        __syncthreads();

        // ---- GEMM2: g_msg = sH @ W2 + b2 ----
        {
            unsigned long long a2[4][2];
#pragma unroll
            for (int e = 0; e < 4; e++) { a2[e][0] = 0ULL; a2[e][1] = 0ULL; }

#pragma unroll 8
            for (int j = 0; j < C_HID; j += 2) {
                ulonglong2 wa = *reinterpret_cast<const ulonglong2*>(&sW2[j * C_OUT + kb]);
                ulonglong2 wb =
                    *reinterpret_cast<const ulonglong2*>(&sW2[(j + 1) * C_OUT + kb]);
#pragma unroll
                for (int e = 0; e < 4; e++) {
                    float2 hv = *reinterpret_cast<const float2*>(&sH[(rb + e) * SH_PITCH + j]);
                    unsigned long long h0 = pack2(hv.x), h1 = pack2(hv.y);
                    a2[e][0] = fma2(h0, wa.x, a2[e][0]);
                    a2[e][1] = fma2(h0, wa.y, a2[e][1]);
                    a2[e][0] = fma2(h1, wb.x, a2[e][0]);
                    a2[e][1] = fma2(h1, wb.y, a2[e][1]);
                }
            }
            float c0 = sb2[kb], c1 = sb2[kb + 1], c2 = sb2[kb + 2], c3 = sb2[kb + 3];
#pragma unroll
            for (int e = 0; e < 4; e++) {
                int n = n0 + rb + e;
                if (n >= N) continue;
                float2 v0 = unpack2(a2[e][0]);
                float2 v1 = unpack2(a2[e][1]);
                float4 r;
                r.x = v0.x + c0; r.y = v0.y + c1; r.z = v1.x + c2; r.w = v1.y + c3;
                *reinterpret_cast<float4*>(&g_msg[(long long)n * C_OUT + kb]) = r;
            }
        }
    }
}

// ---------------------------------------------------------------------------
// K5: gather-aggregate + PReLU + BN stats + GRID-SYNC + BN finalize -> out.
// 16 threads per dst node; each group's node rows stay in registers across
// the spin barrier (all AGG_BLOCKS blocks are co-resident -> no deadlock).
// ---------------------------------------------------------------------------
__global__ __launch_bounds__(NT) void agg_bn_kernel(
    float* __restrict__ out, const float* __restrict__ gamma,
    const float* __restrict__ beta, const float* __restrict__ prelu_w, int N) {
    const float a = prelu_w[0];
    const int q = threadIdx.x & 15;
    const int grp = blockIdx.x * (NT / 16) + (threadIdx.x >> 4);
    const int ngrp = gridDim.x * (NT / 16);

    float4 accs[MAX_NPG];
    float s0 = 0.f, s1 = 0.f, s2 = 0.f, s3 = 0.f;
    float q0 = 0.f, q1 = 0.f, q2 = 0.f, q3 = 0.f;

    int cnt = 0;
    for (int n = grp; n < N; n += ngrp, cnt++) {
        int eb = __ldg(&g_off[n]);
        int ee = __ldg(&g_off[n + 1]);
        float4 acc = *reinterpret_cast<const float4*>(&g_h[(long long)n * C_OUT + q * 4]);
        int e = eb;
        for (; e + 3 < ee; e += 4) {
            int sa = __ldg(&g_esrc[e]);
            int sb = __ldg(&g_esrc[e + 1]);
            int sc = __ldg(&g_esrc[e + 2]);
            int sd = __ldg(&g_esrc[e + 3]);
            float4 m0 = *reinterpret_cast<const float4*>(&g_msg[(long long)sa * C_OUT + q * 4]);
            float4 m1 = *reinterpret_cast<const float4*>(&g_msg[(long long)sb * C_OUT + q * 4]);
            float4 m2 = *reinterpret_cast<const float4*>(&g_msg[(long long)sc * C_OUT + q * 4]);
            float4 m3 = *reinterpret_cast<const float4*>(&g_msg[(long long)sd * C_OUT + q * 4]);
            acc.x += m0.x + m1.x + m2.x + m3.x;
            acc.y += m0.y + m1.y + m2.y + m3.y;
            acc.z += m0.z + m1.z + m2.z + m3.z;
            acc.w += m0.w + m1.w + m2.w + m3.w;
        }
        for (; e < ee; e++) {
            int sa = __ldg(&g_esrc[e]);
            float4 m0 = *reinterpret_cast<const float4*>(&g_msg[(long long)sa * C_OUT + q * 4]);
            acc.x += m0.x; acc.y += m0.y; acc.z += m0.z; acc.w += m0.w;
        }
        acc.x = (acc.x >= 0.f) ? acc.x : a * acc.x;
        acc.y = (acc.y >= 0.f) ? acc.y : a * acc.y;
        acc.z = (acc.z >= 0.f) ? acc.z : a * acc.z;
        acc.w = (acc.w >= 0.f) ? acc.w : a * acc.w;
        accs[cnt] = acc;
        s0 += acc.x; s1 += acc.y; s2 += acc.z; s3 += acc.w;
        q0 += acc.x * acc.x; q1 += acc.y * acc.y;
        q2 += acc.z * acc.z; q3 += acc.w * acc.w;
    }

    // block-level stats reduction -> global atomics
    __shared__ float rs[NT * 4], rq[NT * 4];
    int t = threadIdx.x;
    rs[t * 4 + 0] = s0; rs[t * 4 + 1] = s1; rs[t * 4 + 2] = s2; rs[t * 4 + 3] = s3;
    rq[t * 4 + 0] = q0; rq[t * 4 + 1] = q1; rq[t * 4 + 2] = q2; rq[t * 4 + 3] = q3;
    __syncthreads();
    if (t < 64) {
        int qq = t >> 2, comp = t & 3;
        float ts = 0.f, tq = 0.f;
#pragma unroll
        for (int m = 0; m < 16; m++) {
            int src = (m * 16 + qq) * 4 + comp;
            ts += rs[src];
            tq += rq[src];
        }
        atomicAdd(&g_stats[t], ts);
        atomicAdd(&g_stats[64 + t], tq);
    }
    __syncthreads();

    // grid-wide barrier (all blocks resident by construction)
    if (t == 0) {
        __threadfence();
        atomicAdd(&g_done, 1);
        while (atomicAdd(&g_done, 0) < (int)gridDim.x) __nanosleep(200);
    }
    __syncthreads();
    __threadfence();

    // compute BN scale/shift (threads 0..63)
    __shared__ float sscale[C_OUT], sshift[C_OUT];
    if (t < 64) {
        float invN = 1.f / (float)N;
        float mu = g_stats[t] * invN;
        float var = g_stats[64 + t] * invN - mu * mu;
        float inv = rsqrtf(var + 1e-5f);
        float g = gamma[t] * inv;
        sscale[t] = g;
        sshift[t] = beta[t] - mu * g;
    }
    __syncthreads();

    float4 sc = reinterpret_cast<const float4*>(sscale)[q];
    float4 sh = reinterpret_cast<const float4*>(sshift)[q];
    cnt = 0;
    for (int n = grp; n < N; n += ngrp, cnt++) {
        float4 v = accs[cnt];
        float4 r;
        r.x = fmaf(v.x, sc.x, sh.x);
        r.y = fmaf(v.y, sc.y, sh.y);
        r.z = fmaf(v.z, sc.z, sh.z);
        r.w = fmaf(v.w, sc.w, sh.w);
        *reinterpret_cast<float4*>(&out[(long long)n * C_OUT + q * 4]) = r;
    }
}

// ---------------------------------------------------------------------------
extern "C" void kernel_launch(void* const* d_in, const int* in_sizes, int n_in,
                              void* d_out, int out_size) {
    const float* x = (const float*)d_in[0];
    const void* ei = d_in[1];
    const float* W1 = (const float*)d_in[2];
    const float* b1 = (const float*)d_in[3];
    const float* W2 = (const float*)d_in[4];
    const float* b2 = (const float*)d_in[5];
    const float* Wr = (const float*)d_in[6];
    const float* br = (const float*)d_in[7];
    const float* pw = (const float*)d_in[8];
    const float* gamma = (const float*)d_in[9];
    const float* beta = (const float*)d_in[10];
    float* out = (float*)d_out;

    const int N = in_sizes[0] / C_IN;
    const int E = in_sizes[1] / 2;
    const int numTiles = (N + TILE_N - 1) / TILE_N;

    static int nSM = 0;
    if (nSM == 0) cudaDeviceGetAttribute(&nSM, cudaDevAttrMultiProcessorCount, 0);

    cudaFuncSetAttribute(msg_kernel, cudaFuncAttributeMaxDynamicSharedMemorySize,
                         SMEM_BYTES);

    // sort chain (by dst)
    setup_kernel<<<128, 512>>>(ei, N);
    hist_kernel<<<(E + 511) / 512, 512>>>(ei, E);
    scan_kernel<<<1, 1024>>>(N);
    reorder_kernel<<<(E + 511) / 512, 512>>>(ei, E);

    // persistent per-node MLP (msg) + root transform
    msg_kernel<<<nSM, MT, SMEM_BYTES>>>(x, W1, b1, W2, b2, Wr, br, N, numTiles);

    // gather-aggregate + PReLU + stats + grid-sync + BN -> out
    agg_bn_kernel<<<AGG_BLOCKS, NT>>>(out, gamma, beta, pw, N);
}

// round 10
// speedup vs baseline: 1.0310x; 1.0310x over previous
#include <cuda_runtime.h>
#include <cstdint>

// ---------------------------------------------------------------------------
// GNBlock: h = BN(PReLU(segment_sum(relu(x[src]@W1+b1)@W2+b2, dst) + x@W_root + b_root))
// N=50000, E=800000, C_IN=64, C_HID=128, C_OUT=64
//
// R8 structure (best): per-node msg MLP (persistent) + dst-sorted CSR gather.
// This round: MLP-4 hist/reorder (independent atomic chains), single-block
// scan, x4-unrolled gather. Separate agg and bn kernels (no grid-sync).
// ---------------------------------------------------------------------------

#define N_MAX 50000
#define E_MAX 800000
#define C_IN 64
#define C_HID 128
#define C_OUT 64
#define TILE_N 128
#define MT 512
#define NT 256

__device__ __align__(16) float g_h[N_MAX * C_OUT];    // root -> post-PReLU h
__device__ __align__(16) float g_msg[N_MAX * C_OUT];  // per-node messages
__device__ float g_stats[2 * C_OUT];
__device__ int g_idx64;
__device__ int g_cnt[N_MAX];
__device__ int g_off[N_MAX + 1];
__device__ int g_cursor[N_MAX];
__device__ int g_esrc[E_MAX];  // src list, CSR-ordered by dst

// ---- f32x2 packed helpers ---------------------------------------------------
__device__ __forceinline__ unsigned long long pack2(float v) {
    unsigned long long r;
    unsigned int u = __float_as_uint(v);
    asm("mov.b64 %0, {%1, %2};" : "=l"(r) : "r"(u), "r"(u));
    return r;
}
__device__ __forceinline__ unsigned long long fma2(unsigned long long a,
                                                   unsigned long long b,
                                                   unsigned long long c) {
    unsigned long long d;
    asm("fma.rn.f32x2 %0, %1, %2, %3;" : "=l"(d) : "l"(a), "l"(b), "l"(c));
    return d;
}
__device__ __forceinline__ float2 unpack2(unsigned long long v) {
    unsigned int lo, hi;
    asm("mov.b64 {%0, %1}, %2;" : "=r"(lo), "=r"(hi) : "l"(v));
    float2 f;
    f.x = __uint_as_float(lo);
    f.y = __uint_as_float(hi);
    return f;
}

// ---------------------------------------------------------------------------
// K0: zero g_cnt/g_stats + detect index width
// ---------------------------------------------------------------------------
__global__ void setup_kernel(const void* __restrict__ ei, int N) {
    int gid = blockIdx.x * blockDim.x + threadIdx.x;
    int stride = gridDim.x * blockDim.x;
    for (int i = gid; i < N; i += stride) g_cnt[i] = 0;
    if (gid < 128) g_stats[gid] = 0.f;
    if (blockIdx.x == 0 && threadIdx.x < 32) {
        const long long* p = (const long long*)ei;
        long long v = p[threadIdx.x];
        unsigned ok = __ballot_sync(0xffffffffu, v >= 0 && v < (long long)N);
        if (threadIdx.x == 0) g_idx64 = (ok == 0xffffffffu) ? 1 : 0;
    }
}

// ---------------------------------------------------------------------------
// K1: histogram of dst — 4 edges per thread (4 independent atomic chains)
// ---------------------------------------------------------------------------
__global__ void hist_kernel(const void* __restrict__ ei, int E) {
    int base = (blockIdx.x * blockDim.x + threadIdx.x) * 4;
    if (base >= E) return;
    int d[4];
    int m = (E - base < 4) ? (E - base) : 4;
    if (g_idx64) {
        const long long* p = (const long long*)ei + E;
#pragma unroll
        for (int j = 0; j < 4; j++)
            if (j < m) d[j] = (int)__ldg(&p[base + j]);
    } else {
        const int* p = (const int*)ei + E;
#pragma unroll
        for (int j = 0; j < 4; j++)
            if (j < m) d[j] = __ldg(&p[base + j]);
    }
#pragma unroll
    for (int j = 0; j < 4; j++)
        if (j < m) atomicAdd(&g_cnt[d[j]], 1);
}

// ---------------------------------------------------------------------------
// K2: SINGLE-BLOCK exclusive scan (1024 threads, each owns a serial chunk)
// ---------------------------------------------------------------------------
__global__ __launch_bounds__(1024) void scan_kernel(int N) {
    const int T = 1024;
    int t = threadIdx.x;
    int lane = t & 31, wid = t >> 5;
    int chunk = (N + T - 1) / T;
    int beg = t * chunk;
    int end = beg + chunk;
    if (beg > N) beg = N;
    if (end > N) end = N;

    int sum = 0;
    for (int i = beg; i < end; i++) sum += g_cnt[i];

    int inc = sum;
#pragma unroll
    for (int o = 1; o < 32; o <<= 1) {
        int u = __shfl_up_sync(0xffffffffu, inc, o);
        if (lane >= o) inc += u;
    }
    __shared__ int wsum[32];
    if (lane == 31) wsum[wid] = inc;
    __syncthreads();
    if (wid == 0) {
        int v = wsum[lane];
        int wi = v;
#pragma unroll
        for (int o = 1; o < 32; o <<= 1) {
            int u = __shfl_up_sync(0xffffffffu, wi, o);
            if (lane >= o) wi += u;
        }
        wsum[lane] = wi - v;  // exclusive warp prefix
    }
    __syncthreads();
    int run = wsum[wid] + inc - sum;
    for (int i = beg; i < end; i++) {
        int c = g_cnt[i];
        g_off[i] = run;
        g_cursor[i] = run;
        run += c;
    }
    if (end == N) g_off[N] = run;
}

// ---------------------------------------------------------------------------
// K3: bucket edges by dst — 4 edges per thread (4 independent atomic chains)
// ---------------------------------------------------------------------------
__global__ void reorder_kernel(const void* __restrict__ ei, int E) {
    int base = (blockIdx.x * blockDim.x + threadIdx.x) * 4;
    if (base >= E) return;
    int s[4], d[4], pos[4];
    int m = (E - base < 4) ? (E - base) : 4;
    if (g_idx64) {
        const long long* p = (const long long*)ei;
#pragma unroll
        for (int j = 0; j < 4; j++)
            if (j < m) {
                s[j] = (int)__ldg(&p[base + j]);
                d[j] = (int)__ldg(&p[E + base + j]);
            }
    } else {
        const int* p = (const int*)ei;
#pragma unroll
        for (int j = 0; j < 4; j++)
            if (j < m) {
                s[j] = __ldg(&p[base + j]);
                d[j] = __ldg(&p[E + base + j]);
            }
    }
#pragma unroll
    for (int j = 0; j < 4; j++)
        if (j < m) pos[j] = atomicAdd(&g_cursor[d[j]], 1);
#pragma unroll
    for (int j = 0; j < 4; j++)
        if (j < m) g_esrc[pos[j]] = s[j];
}

// ---------------------------------------------------------------------------
// K4: PERSISTENT fused per-node kernel (weights staged once per block):
//   msg[n] = relu(x[n]@W1 + b1) @ W2 + b2  -> g_msg
//   h[n]   = x[n]@W_root + b_root          -> g_h
// ---------------------------------------------------------------------------
#define SX_PITCH 68
#define SH_PITCH 132
#define SMEM_FLOATS (8192 + 8192 + 4096 + TILE_N * SX_PITCH + TILE_N * SH_PITCH + 256)
#define SMEM_BYTES (SMEM_FLOATS * 4)

__global__ __launch_bounds__(MT) void msg_kernel(
    const float* __restrict__ x, const float* __restrict__ W1,
    const float* __restrict__ b1, const float* __restrict__ W2,
    const float* __restrict__ b2, const float* __restrict__ Wr,
    const float* __restrict__ br, int N, int numTiles) {
    extern __shared__ float sm[];
    float* sW1 = sm;                      // 64 x 128
    float* sW2 = sW1 + 64 * 128;          // 128 x 64
    float* sWr = sW2 + 128 * 64;          // 64 x 64
    float* sX = sWr + 64 * 64;            // 128 x 68 (padded)
    float* sH = sX + TILE_N * SX_PITCH;   // 128 x 132 (padded)
    float* sb1 = sH + TILE_N * SH_PITCH;  // 128
    float* sb2 = sb1 + 128;               // 64
    float* sbr = sb2 + 64;                // 64

    const int tid = threadIdx.x;

    for (int i = tid; i < 2048; i += MT)
        reinterpret_cast<float4*>(sW1)[i] = reinterpret_cast<const float4*>(W1)[i];
    for (int i = tid; i < 2048; i += MT)
        reinterpret_cast<float4*>(sW2)[i] = reinterpret_cast<const float4*>(W2)[i];
    for (int i = tid; i < 1024; i += MT)
        reinterpret_cast<float4*>(sWr)[i] = reinterpret_cast<const float4*>(Wr)[i];
    if (tid < 128) sb1[tid] = b1[tid];
    else if (tid < 192) sb2[tid - 128] = b2[tid - 128];
    else if (tid < 256) sbr[tid - 192] = br[tid - 192];

    const int hg = tid & 15;
    const int rg = tid >> 4;
    const int hb = hg * 8;
    const int kb = hg * 4;
    const int rb = rg * 4;

    for (int tile = blockIdx.x; tile < numTiles; tile += gridDim.x) {
        const int n0 = tile * TILE_N;
        __syncthreads();  // prior tile's sH readers done; weights staged

        for (int i = tid; i < TILE_N * 16; i += MT) {
            int r = i >> 4, q = i & 15;
            int n = n0 + r;
            if (n >= N) n = N - 1;
            float4 v = reinterpret_cast<const float4*>(x + (long long)n * C_IN)[q];
            *reinterpret_cast<float4*>(&sX[r * SX_PITCH + q * 4]) = v;
        }
        __syncthreads();

        // ---- GEMM1: sH = relu(sX @ W1 + b1) ----
        {
            unsigned long long acc[4][4];
#pragma unroll
            for (int e = 0; e < 4; e++)
#pragma unroll
                for (int p = 0; p < 4; p++) acc[e][p] = 0ULL;

#pragma unroll 8
            for (int k = 0; k < C_IN; k += 2) {
                ulonglong2 wa0 = *reinterpret_cast<const ulonglong2*>(&sW1[k * C_HID + hb]);
                ulonglong2 wa1 =
                    *reinterpret_cast<const ulonglong2*>(&sW1[k * C_HID + hb + 4]);
                ulonglong2 wb0 =
                    *reinterpret_cast<const ulonglong2*>(&sW1[(k + 1) * C_HID + hb]);
                ulonglong2 wb1 =
                    *reinterpret_cast<const ulonglong2*>(&sW1[(k + 1) * C_HID + hb + 4]);
#pragma unroll
                for (int e = 0; e < 4; e++) {
                    float2 xv = *reinterpret_cast<const float2*>(&sX[(rb + e) * SX_PITCH + k]);
                    unsigned long long x0 = pack2(xv.x), x1 = pack2(xv.y);
                    acc[e][0] = fma2(x0, wa0.x, acc[e][0]);
                    acc[e][1] = fma2(x0, wa0.y, acc[e][1]);
                    acc[e][2] = fma2(x0, wa1.x, acc[e][2]);
                    acc[e][3] = fma2(x0, wa1.y, acc[e][3]);
                    acc[e][0] = fma2(x1, wb0.x, acc[e][0]);
                    acc[e][1] = fma2(x1, wb0.y, acc[e][1]);
                    acc[e][2] = fma2(x1, wb1.x, acc[e][2]);
                    acc[e][3] = fma2(x1, wb1.y, acc[e][3]);
                }
            }
#pragma unroll
            for (int e = 0; e < 4; e++) {
#pragma unroll
                for (int p = 0; p < 4; p++) {
                    float2 v = unpack2(acc[e][p]);
                    v.x = fmaxf(v.x + sb1[hb + 2 * p], 0.f);
                    v.y = fmaxf(v.y + sb1[hb + 2 * p + 1], 0.f);
                    *reinterpret_cast<float2*>(&sH[(rb + e) * SH_PITCH + hb + 2 * p]) = v;
                }
            }
        }

        // ---- GEMM3: g_h = sX @ W_root + b_root ----
        {
            unsigned long long a3[4][2];
#pragma unroll
            for (int e = 0; e < 4; e++) { a3[e][0] = 0ULL; a3[e][1] = 0ULL; }

#pragma unroll 8
            for (int k = 0; k < C_IN; k += 2) {
                ulonglong2 wa = *reinterpret_cast<const ulonglong2*>(&sWr[k * C_OUT + kb]);
                ulonglong2 wb =
                    *reinterpret_cast<const ulonglong2*>(&sWr[(k + 1) * C_OUT + kb]);
#pragma unroll
                for (int e = 0; e < 4; e++) {
                    float2 xv = *reinterpret_cast<const float2*>(&sX[(rb + e) * SX_PITCH + k]);
                    unsigned long long x0 = pack2(xv.x), x1 = pack2(xv.y);
                    a3[e][0] = fma2(x0, wa.x, a3[e][0]);
                    a3[e][1] = fma2(x0, wa.y, a3[e][1]);
                    a3[e][0] = fma2(x1, wb.x, a3[e][0]);
                    a3[e][1] = fma2(x1, wb.y, a3[e][1]);
                }
            }
            float c0 = sbr[kb], c1 = sbr[kb + 1], c2 = sbr[kb + 2], c3 = sbr[kb + 3];
#pragma unroll
            for (int e = 0; e < 4; e++) {
                int n = n0 + rb + e;
                if (n >= N) continue;
                float2 v0 = unpack2(a3[e][0]);
                float2 v1 = unpack2(a3[e][1]);
                float4 r;
                r.x = v0.x + c0; r.y = v0.y + c1; r.z = v1.x + c2; r.w = v1.y + c3;
                *reinterpret_cast<float4*>(&g_h[(long long)n * C_OUT + kb]) = r;
            }
        }
        __syncthreads();

        // ---- GEMM2: g_msg = sH @ W2 + b2 ----
        {
            unsigned long long a2[4][2];
#pragma unroll
            for (int e = 0; e < 4; e++) { a2[e][0] = 0ULL; a2[e][1] = 0ULL; }

#pragma unroll 8
            for (int j = 0; j < C_HID; j += 2) {
                ulonglong2 wa = *reinterpret_cast<const ulonglong2*>(&sW2[j * C_OUT + kb]);
                ulonglong2 wb =
                    *reinterpret_cast<const ulonglong2*>(&sW2[(j + 1) * C_OUT + kb]);
#pragma unroll
                for (int e = 0; e < 4; e++) {
                    float2 hv = *reinterpret_cast<const float2*>(&sH[(rb + e) * SH_PITCH + j]);
                    unsigned long long h0 = pack2(hv.x), h1 = pack2(hv.y);
                    a2[e][0] = fma2(h0, wa.x, a2[e][0]);
                    a2[e][1] = fma2(h0, wa.y, a2[e][1]);
                    a2[e][0] = fma2(h1, wb.x, a2[e][0]);
                    a2[e][1] = fma2(h1, wb.y, a2[e][1]);
                }
            }
            float c0 = sb2[kb], c1 = sb2[kb + 1], c2 = sb2[kb + 2], c3 = sb2[kb + 3];
#pragma unroll
            for (int e = 0; e < 4; e++) {
                int n = n0 + rb + e;
                if (n >= N) continue;
                float2 v0 = unpack2(a2[e][0]);
                float2 v1 = unpack2(a2[e][1]);
                float4 r;
                r.x = v0.x + c0; r.y = v0.y + c1; r.z = v1.x + c2; r.w = v1.y + c3;
                *reinterpret_cast<float4*>(&g_msg[(long long)n * C_OUT + kb]) = r;
            }
        }
    }
}

// ---------------------------------------------------------------------------
// K5: gather-aggregate + PReLU + BN-stats (16 threads per dst node, x4 unroll)
// ---------------------------------------------------------------------------
__global__ __launch_bounds__(NT) void agg_kernel(const float* __restrict__ prelu_w,
                                                 int N) {
    const float a = prelu_w[0];
    const int q = threadIdx.x & 15;
    const int grp = blockIdx.x * (NT / 16) + (threadIdx.x >> 4);
    const int ngrp = gridDim.x * (NT / 16);

    float s0 = 0.f, s1 = 0.f, s2 = 0.f, s3 = 0.f;
    float q0 = 0.f, q1 = 0.f, q2 = 0.f, q3 = 0.f;

    for (int n = grp; n < N; n += ngrp) {
        int eb = __ldg(&g_off[n]);
        int ee = __ldg(&g_off[n + 1]);
        float4 acc = *reinterpret_cast<const float4*>(&g_h[(long long)n * C_OUT + q * 4]);
        int e = eb;
        for (; e + 3 < ee; e += 4) {
            int sa = __ldg(&g_esrc[e]);
            int sb = __ldg(&g_esrc[e + 1]);
            int sc = __ldg(&g_esrc[e + 2]);
            int sd = __ldg(&g_esrc[e + 3]);
            float4 m0 = *reinterpret_cast<const float4*>(&g_msg[(long long)sa * C_OUT + q * 4]);
            float4 m1 = *reinterpret_cast<const float4*>(&g_msg[(long long)sb * C_OUT + q * 4]);
            float4 m2 = *reinterpret_cast<const float4*>(&g_msg[(long long)sc * C_OUT + q * 4]);
            float4 m3 = *reinterpret_cast<const float4*>(&g_msg[(long long)sd * C_OUT + q * 4]);
            acc.x += m0.x + m1.x + m2.x + m3.x;
            acc.y += m0.y + m1.y + m2.y + m3.y;
            acc.z += m0.z + m1.z + m2.z + m3.z;
            acc.w += m0.w + m1.w + m2.w + m3.w;
        }
        for (; e < ee; e++) {
            int sa = __ldg(&g_esrc[e]);
            float4 m0 = *reinterpret_cast<const float4*>(&g_msg[(long long)sa * C_OUT + q * 4]);
            acc.x += m0.x; acc.y += m0.y; acc.z += m0.z; acc.w += m0.w;
        }
        acc.x = (acc.x >= 0.f) ? acc.x : a * acc.x;
        acc.y = (acc.y >= 0.f) ? acc.y : a * acc.y;
        acc.z = (acc.z >= 0.f) ? acc.z : a * acc.z;
        acc.w = (acc.w >= 0.f) ? acc.w : a * acc.w;
        *reinterpret_cast<float4*>(&g_h[(long long)n * C_OUT + q * 4]) = acc;
        s0 += acc.x; s1 += acc.y; s2 += acc.z; s3 += acc.w;
        q0 += acc.x * acc.x; q1 += acc.y * acc.y;
        q2 += acc.z * acc.z; q3 += acc.w * acc.w;
    }

    __shared__ float rs[NT * 4], rq[NT * 4];
    int t = threadIdx.x;
    rs[t * 4 + 0] = s0; rs[t * 4 + 1] = s1; rs[t * 4 + 2] = s2; rs[t * 4 + 3] = s3;
    rq[t * 4 + 0] = q0; rq[t * 4 + 1] = q1; rq[t * 4 + 2] = q2; rq[t * 4 + 3] = q3;
    __syncthreads();
    if (t < 64) {
        int qq = t >> 2, comp = t & 3;
        float ts = 0.f, tq = 0.f;
#pragma unroll
        for (int m = 0; m < 16; m++) {
            int src = (m * 16 + qq) * 4 + comp;
            ts += rs[src];
            tq += rq[src];
        }
        atomicAdd(&g_stats[t], ts);
        atomicAdd(&g_stats[64 + t], tq);
    }
}

// ---------------------------------------------------------------------------
// K6: finalize BN (g_h already holds PReLU'd values) -> out
// ---------------------------------------------------------------------------
__global__ void bn_kernel(float* __restrict__ out, const float* __restrict__ gamma,
                          const float* __restrict__ beta, int N) {
    __shared__ float sscale[C_OUT], sshift[C_OUT];
    if (threadIdx.x < C_OUT) {
        float invN = 1.f / (float)N;
        float mu = g_stats[threadIdx.x] * invN;
        float var = g_stats[64 + threadIdx.x] * invN - mu * mu;
        float inv = rsqrtf(var + 1e-5f);
        float g = gamma[threadIdx.x] * inv;
        sscale[threadIdx.x] = g;
        sshift[threadIdx.x] = beta[threadIdx.x] - mu * g;
    }
    __syncthreads();
    const int total4 = N * (C_OUT / 4);
    const int stride = gridDim.x * blockDim.x;
    const float4* gh4 = reinterpret_cast<const float4*>(g_h);
    float4* o4 = reinterpret_cast<float4*>(out);
    for (int i = blockIdx.x * blockDim.x + threadIdx.x; i < total4; i += stride) {
        int q = (i & 15);
        float4 sc = reinterpret_cast<const float4*>(sscale)[q];
        float4 sh = reinterpret_cast<const float4*>(sshift)[q];
        float4 v = gh4[i];
        float4 r;
        r.x = fmaf(v.x, sc.x, sh.x);
        r.y = fmaf(v.y, sc.y, sh.y);
        r.z = fmaf(v.z, sc.z, sh.z);
        r.w = fmaf(v.w, sc.w, sh.w);
        o4[i] = r;
    }
}

// ---------------------------------------------------------------------------
extern "C" void kernel_launch(void* const* d_in, const int* in_sizes, int n_in,
                              void* d_out, int out_size) {
    const float* x = (const float*)d_in[0];
    const void* ei = d_in[1];
    const float* W1 = (const float*)d_in[2];
    const float* b1 = (const float*)d_in[3];
    const float* W2 = (const float*)d_in[4];
    const float* b2 = (const float*)d_in[5];
    const float* Wr = (const float*)d_in[6];
    const float* br = (const float*)d_in[7];
    const float* pw = (const float*)d_in[8];
    const float* gamma = (const float*)d_in[9];
    const float* beta = (const float*)d_in[10];
    float* out = (float*)d_out;

    const int N = in_sizes[0] / C_IN;
    const int E = in_sizes[1] / 2;
    const int numTiles = (N + TILE_N - 1) / TILE_N;
    const int E4 = (E + 3) / 4;  // threads needed at 4 edges/thread

    static int nSM = 0;
    if (nSM == 0) cudaDeviceGetAttribute(&nSM, cudaDevAttrMultiProcessorCount, 0);

    cudaFuncSetAttribute(msg_kernel, cudaFuncAttributeMaxDynamicSharedMemorySize,
                         SMEM_BYTES);

    // sort chain (by dst)
    setup_kernel<<<128, 512>>>(ei, N);
    hist_kernel<<<(E4 + 255) / 256, 256>>>(ei, E);
    scan_kernel<<<1, 1024>>>(N);
    reorder_kernel<<<(E4 + 255) / 256, 256>>>(ei, E);

    // persistent per-node MLP (msg) + root transform
    msg_kernel<<<nSM, MT, SMEM_BYTES>>>(x, W1, b1, W2, b2, Wr, br, N, numTiles);

    // gather-aggregate + PReLU + stats
    agg_kernel<<<592, NT>>>(pw, N);

    // BN finalize
    bn_kernel<<<592, NT>>>(out, gamma, beta, N);
}

// round 11
// speedup vs baseline: 1.5935x; 1.5456x over previous
#include <cuda_runtime.h>
#include <cstdint>

// ---------------------------------------------------------------------------
// GNBlock: h = BN(PReLU(segment_sum(relu(x[src]@W1+b1)@W2+b2, dst) + x@W_root + b_root))
// N=50000, E=800000, C_IN=64, C_HID=128, C_OUT=64
//
// Best-of-measured assembly (NO edge sort):
//   setup: zero stats + dtype probe
//   msg (persistent): msg[n]=MLP(x[n]) -> g_msg ; h[n]=x[n]@Wr+br -> g_h
//   scatter: g_h[dst] += g_msg[src] via red.global.add.v4 (R4's 49.5us kernel)
//   stats: PReLU in place + per-channel sum/sumsq
//   bn: normalize -> out
// ---------------------------------------------------------------------------

#define N_MAX 50000
#define C_IN 64
#define C_HID 128
#define C_OUT 64
#define TILE_N 128
#define MT 512
#define NT 256

__device__ __align__(16) float g_h[N_MAX * C_OUT];    // root -> h (post-PReLU)
__device__ __align__(16) float g_msg[N_MAX * C_OUT];  // per-node messages
__device__ float g_stats[2 * C_OUT];
__device__ int g_idx64;

// ---- f32x2 packed helpers ---------------------------------------------------
__device__ __forceinline__ unsigned long long pack2(float v) {
    unsigned long long r;
    unsigned int u = __float_as_uint(v);
    asm("mov.b64 %0, {%1, %2};" : "=l"(r) : "r"(u), "r"(u));
    return r;
}
__device__ __forceinline__ unsigned long long fma2(unsigned long long a,
                                                   unsigned long long b,
                                                   unsigned long long c) {
    unsigned long long d;
    asm("fma.rn.f32x2 %0, %1, %2, %3;" : "=l"(d) : "l"(a), "l"(b), "l"(c));
    return d;
}
__device__ __forceinline__ float2 unpack2(unsigned long long v) {
    unsigned int lo, hi;
    asm("mov.b64 {%0, %1}, %2;" : "=r"(lo), "=r"(hi) : "l"(v));
    float2 f;
    f.x = __uint_as_float(lo);
    f.y = __uint_as_float(hi);
    return f;
}

// ---------------------------------------------------------------------------
// K0: zero stats + detect index width
// ---------------------------------------------------------------------------
__global__ void setup_kernel(const void* __restrict__ ei, int N) {
    int tid = threadIdx.x;
    if (tid < 128) g_stats[tid] = 0.f;
    if (tid >= 128 && tid < 160) {
        const long long* p = (const long long*)ei;
        long long v = p[tid - 128];
        unsigned ok = __ballot_sync(0xffffffffu, v >= 0 && v < (long long)N);
        if (tid == 128) g_idx64 = (ok == 0xffffffffu) ? 1 : 0;
    }
}

// ---------------------------------------------------------------------------
// K1: PERSISTENT fused per-node kernel (weights staged once per block):
//   msg[n] = relu(x[n]@W1 + b1) @ W2 + b2  -> g_msg
//   h[n]   = x[n]@W_root + b_root          -> g_h
// ---------------------------------------------------------------------------
#define SX_PITCH 68
#define SH_PITCH 132
#define SMEM_FLOATS (8192 + 8192 + 4096 + TILE_N * SX_PITCH + TILE_N * SH_PITCH + 256)
#define SMEM_BYTES (SMEM_FLOATS * 4)

__global__ __launch_bounds__(MT) void msg_kernel(
    const float* __restrict__ x, const float* __restrict__ W1,
    const float* __restrict__ b1, const float* __restrict__ W2,
    const float* __restrict__ b2, const float* __restrict__ Wr,
    const float* __restrict__ br, int N, int numTiles) {
    extern __shared__ float sm[];
    float* sW1 = sm;                      // 64 x 128
    float* sW2 = sW1 + 64 * 128;          // 128 x 64
    float* sWr = sW2 + 128 * 64;          // 64 x 64
    float* sX = sWr + 64 * 64;            // 128 x 68 (padded)
    float* sH = sX + TILE_N * SX_PITCH;   // 128 x 132 (padded)
    float* sb1 = sH + TILE_N * SH_PITCH;  // 128
    float* sb2 = sb1 + 128;               // 64
    float* sbr = sb2 + 64;                // 64

    const int tid = threadIdx.x;

    for (int i = tid; i < 2048; i += MT)
        reinterpret_cast<float4*>(sW1)[i] = reinterpret_cast<const float4*>(W1)[i];
    for (int i = tid; i < 2048; i += MT)
        reinterpret_cast<float4*>(sW2)[i] = reinterpret_cast<const float4*>(W2)[i];
    for (int i = tid; i < 1024; i += MT)
        reinterpret_cast<float4*>(sWr)[i] = reinterpret_cast<const float4*>(Wr)[i];
    if (tid < 128) sb1[tid] = b1[tid];
    else if (tid < 192) sb2[tid - 128] = b2[tid - 128];
    else if (tid < 256) sbr[tid - 192] = br[tid - 192];

    const int hg = tid & 15;
    const int rg = tid >> 4;
    const int hb = hg * 8;
    const int kb = hg * 4;
    const int rb = rg * 4;

    for (int tile = blockIdx.x; tile < numTiles; tile += gridDim.x) {
        const int n0 = tile * TILE_N;
        __syncthreads();  // prior tile's sH readers done; weights staged

        for (int i = tid; i < TILE_N * 16; i += MT) {
            int r = i >> 4, q = i & 15;
            int n = n0 + r;
            if (n >= N) n = N - 1;
            float4 v = reinterpret_cast<const float4*>(x + (long long)n * C_IN)[q];
            *reinterpret_cast<float4*>(&sX[r * SX_PITCH + q * 4]) = v;
        }
        __syncthreads();

        // ---- GEMM1: sH = relu(sX @ W1 + b1) ----
        {
            unsigned long long acc[4][4];
#pragma unroll
            for (int e = 0; e < 4; e++)
#pragma unroll
                for (int p = 0; p < 4; p++) acc[e][p] = 0ULL;

#pragma unroll 8
            for (int k = 0; k < C_IN; k += 2) {
                ulonglong2 wa0 = *reinterpret_cast<const ulonglong2*>(&sW1[k * C_HID + hb]);
                ulonglong2 wa1 =
                    *reinterpret_cast<const ulonglong2*>(&sW1[k * C_HID + hb + 4]);
                ulonglong2 wb0 =
                    *reinterpret_cast<const ulonglong2*>(&sW1[(k + 1) * C_HID + hb]);
                ulonglong2 wb1 =
                    *reinterpret_cast<const ulonglong2*>(&sW1[(k + 1) * C_HID + hb + 4]);
#pragma unroll
                for (int e = 0; e < 4; e++) {
                    float2 xv = *reinterpret_cast<const float2*>(&sX[(rb + e) * SX_PITCH + k]);
                    unsigned long long x0 = pack2(xv.x), x1 = pack2(xv.y);
                    acc[e][0] = fma2(x0, wa0.x, acc[e][0]);
                    acc[e][1] = fma2(x0, wa0.y, acc[e][1]);
                    acc[e][2] = fma2(x0, wa1.x, acc[e][2]);
                    acc[e][3] = fma2(x0, wa1.y, acc[e][3]);
                    acc[e][0] = fma2(x1, wb0.x, acc[e][0]);
                    acc[e][1] = fma2(x1, wb0.y, acc[e][1]);
                    acc[e][2] = fma2(x1, wb1.x, acc[e][2]);
                    acc[e][3] = fma2(x1, wb1.y, acc[e][3]);
                }
            }
#pragma unroll
            for (int e = 0; e < 4; e++) {
#pragma unroll
                for (int p = 0; p < 4; p++) {
                    float2 v = unpack2(acc[e][p]);
                    v.x = fmaxf(v.x + sb1[hb + 2 * p], 0.f);
                    v.y = fmaxf(v.y + sb1[hb + 2 * p + 1], 0.f);
                    *reinterpret_cast<float2*>(&sH[(rb + e) * SH_PITCH + hb + 2 * p]) = v;
                }
            }
        }

        // ---- GEMM3: g_h = sX @ W_root + b_root ----
        {
            unsigned long long a3[4][2];
#pragma unroll
            for (int e = 0; e < 4; e++) { a3[e][0] = 0ULL; a3[e][1] = 0ULL; }

#pragma unroll 8
            for (int k = 0; k < C_IN; k += 2) {
                ulonglong2 wa = *reinterpret_cast<const ulonglong2*>(&sWr[k * C_OUT + kb]);
                ulonglong2 wb =
                    *reinterpret_cast<const ulonglong2*>(&sWr[(k + 1) * C_OUT + kb]);
#pragma unroll
                for (int e = 0; e < 4; e++) {
                    float2 xv = *reinterpret_cast<const float2*>(&sX[(rb + e) * SX_PITCH + k]);
                    unsigned long long x0 = pack2(xv.x), x1 = pack2(xv.y);
                    a3[e][0] = fma2(x0, wa.x, a3[e][0]);
                    a3[e][1] = fma2(x0, wa.y, a3[e][1]);
                    a3[e][0] = fma2(x1, wb.x, a3[e][0]);
                    a3[e][1] = fma2(x1, wb.y, a3[e][1]);
                }
            }
            float c0 = sbr[kb], c1 = sbr[kb + 1], c2 = sbr[kb + 2], c3 = sbr[kb + 3];
#pragma unroll
            for (int e = 0; e < 4; e++) {
                int n = n0 + rb + e;
                if (n >= N) continue;
                float2 v0 = unpack2(a3[e][0]);
                float2 v1 = unpack2(a3[e][1]);
                float4 r;
                r.x = v0.x + c0; r.y = v0.y + c1; r.z = v1.x + c2; r.w = v1.y + c3;
                *reinterpret_cast<float4*>(&g_h[(long long)n * C_OUT + kb]) = r;
            }
        }
        __syncthreads();

        // ---- GEMM2: g_msg = sH @ W2 + b2 ----
        {
            unsigned long long a2[4][2];
#pragma unroll
            for (int e = 0; e < 4; e++) { a2[e][0] = 0ULL; a2[e][1] = 0ULL; }

#pragma unroll 8
            for (int j = 0; j < C_HID; j += 2) {
                ulonglong2 wa = *reinterpret_cast<const ulonglong2*>(&sW2[j * C_OUT + kb]);
                ulonglong2 wb =
                    *reinterpret_cast<const ulonglong2*>(&sW2[(j + 1) * C_OUT + kb]);
#pragma unroll
                for (int e = 0; e < 4; e++) {
                    float2 hv = *reinterpret_cast<const float2*>(&sH[(rb + e) * SH_PITCH + j]);
                    unsigned long long h0 = pack2(hv.x), h1 = pack2(hv.y);
                    a2[e][0] = fma2(h0, wa.x, a2[e][0]);
                    a2[e][1] = fma2(h0, wa.y, a2[e][1]);
                    a2[e][0] = fma2(h1, wb.x, a2[e][0]);
                    a2[e][1] = fma2(h1, wb.y, a2[e][1]);
                }
            }
            float c0 = sb2[kb], c1 = sb2[kb + 1], c2 = sb2[kb + 2], c3 = sb2[kb + 3];
#pragma unroll
            for (int e = 0; e < 4; e++) {
                int n = n0 + rb + e;
                if (n >= N) continue;
                float2 v0 = unpack2(a2[e][0]);
                float2 v1 = unpack2(a2[e][1]);
                float4 r;
                r.x = v0.x + c0; r.y = v0.y + c1; r.z = v1.x + c2; r.w = v1.y + c3;
                *reinterpret_cast<float4*>(&g_msg[(long long)n * C_OUT + kb]) = r;
            }
        }
    }
}

// ---------------------------------------------------------------------------
// K2: scatter  g_h[dst] += g_msg[src]  (16 threads per edge, float4 each).
// Per-thread index loads are broadcast-coalesced (same address within the
// 16-group -> one sector). Exactly the R4 kernel measured at 49.5us.
// ---------------------------------------------------------------------------
__global__ __launch_bounds__(NT) void scatter_kernel(const void* __restrict__ ei_raw,
                                                     int E) {
    long long idx = (long long)blockIdx.x * NT + threadIdx.x;
    long long total = (long long)E * 16;
    if (idx >= total) return;
    int e = (int)(idx >> 4);
    int q = (int)(idx & 15);
    int s, d;
    if (g_idx64) {
        const long long* p = (const long long*)ei_raw;
        s = (int)__ldg(&p[e]);
        d = (int)__ldg(&p[E + e]);
    } else {
        const int* p = (const int*)ei_raw;
        s = __ldg(&p[e]);
        d = __ldg(&p[E + e]);
    }
    float4 v = *reinterpret_cast<const float4*>(&g_msg[(long long)s * C_OUT + q * 4]);
    float* pd = &g_h[(long long)d * C_OUT + q * 4];
    asm volatile("red.global.add.v4.f32 [%0], {%1,%2,%3,%4};"
                 :: "l"(pd), "f"(v.x), "f"(v.y), "f"(v.z), "f"(v.w)
                 : "memory");
}

// ---------------------------------------------------------------------------
// K3: PReLU in-place (float4) + per-channel sum / sumsq partials
// ---------------------------------------------------------------------------
__global__ void prelu_stats_kernel(const float* __restrict__ prelu_w, int N) {
    const float a = prelu_w[0];
    const int total4 = N * (C_OUT / 4);
    const int stride = gridDim.x * blockDim.x;
    float4* gh4 = reinterpret_cast<float4*>(g_h);
    float s0 = 0.f, s1 = 0.f, s2 = 0.f, s3 = 0.f;
    float q0 = 0.f, q1 = 0.f, q2 = 0.f, q3 = 0.f;
    // stride is a multiple of 16 -> each thread touches a fixed channel quad
    for (int i = blockIdx.x * blockDim.x + threadIdx.x; i < total4; i += stride) {
        float4 v = gh4[i];
        v.x = (v.x >= 0.f) ? v.x : a * v.x;
        v.y = (v.y >= 0.f) ? v.y : a * v.y;
        v.z = (v.z >= 0.f) ? v.z : a * v.z;
        v.w = (v.w >= 0.f) ? v.w : a * v.w;
        gh4[i] = v;
        s0 += v.x; s1 += v.y; s2 += v.z; s3 += v.w;
        q0 += v.x * v.x; q1 += v.y * v.y; q2 += v.z * v.z; q3 += v.w * v.w;
    }
    __shared__ float rs[NT * 4], rq[NT * 4];
    int t = threadIdx.x;
    rs[t * 4 + 0] = s0; rs[t * 4 + 1] = s1; rs[t * 4 + 2] = s2; rs[t * 4 + 3] = s3;
    rq[t * 4 + 0] = q0; rq[t * 4 + 1] = q1; rq[t * 4 + 2] = q2; rq[t * 4 + 3] = q3;
    __syncthreads();
    if (t < 64) {
        int qq = t >> 2, comp = t & 3;
        float ts = 0.f, tq = 0.f;
#pragma unroll
        for (int m = 0; m < 16; m++) {
            int src = (m * 16 + qq) * 4 + comp;
            ts += rs[src];
            tq += rq[src];
        }
        atomicAdd(&g_stats[t], ts);
        atomicAdd(&g_stats[64 + t], tq);
    }
}

// ---------------------------------------------------------------------------
// K4: finalize BN (g_h already PReLU'd) -> out
// ---------------------------------------------------------------------------
__global__ void bn_kernel(float* __restrict__ out, const float* __restrict__ gamma,
                          const float* __restrict__ beta, int N) {
    __shared__ float sscale[C_OUT], sshift[C_OUT];
    if (threadIdx.x < C_OUT) {
        float invN = 1.f / (float)N;
        float mu = g_stats[threadIdx.x] * invN;
        float var = g_stats[64 + threadIdx.x] * invN - mu * mu;
        float inv = rsqrtf(var + 1e-5f);
        float g = gamma[threadIdx.x] * inv;
        sscale[threadIdx.x] = g;
        sshift[threadIdx.x] = beta[threadIdx.x] - mu * g;
    }
    __syncthreads();
    const int total4 = N * (C_OUT / 4);
    const int stride = gridDim.x * blockDim.x;
    const float4* gh4 = reinterpret_cast<const float4*>(g_h);
    float4* o4 = reinterpret_cast<float4*>(out);
    for (int i = blockIdx.x * blockDim.x + threadIdx.x; i < total4; i += stride) {
        int q = (i & 15);
        float4 sc = reinterpret_cast<const float4*>(sscale)[q];
        float4 sh = reinterpret_cast<const float4*>(sshift)[q];
        float4 v = gh4[i];
        float4 r;
        r.x = fmaf(v.x, sc.x, sh.x);
        r.y = fmaf(v.y, sc.y, sh.y);
        r.z = fmaf(v.z, sc.z, sh.z);
        r.w = fmaf(v.w, sc.w, sh.w);
        o4[i] = r;
    }
}

// ---------------------------------------------------------------------------
extern "C" void kernel_launch(void* const* d_in, const int* in_sizes, int n_in,
                              void* d_out, int out_size) {
    const float* x = (const float*)d_in[0];
    const void* ei = d_in[1];
    const float* W1 = (const float*)d_in[2];
    const float* b1 = (const float*)d_in[3];
    const float* W2 = (const float*)d_in[4];
    const float* b2 = (const float*)d_in[5];
    const float* Wr = (const float*)d_in[6];
    const float* br = (const float*)d_in[7];
    const float* pw = (const float*)d_in[8];
    const float* gamma = (const float*)d_in[9];
    const float* beta = (const float*)d_in[10];
    float* out = (float*)d_out;

    const int N = in_sizes[0] / C_IN;
    const int E = in_sizes[1] / 2;
    const int numTiles = (N + TILE_N - 1) / TILE_N;

    static int nSM = 0;
    if (nSM == 0) cudaDeviceGetAttribute(&nSM, cudaDevAttrMultiProcessorCount, 0);

    cudaFuncSetAttribute(msg_kernel, cudaFuncAttributeMaxDynamicSharedMemorySize,
                         SMEM_BYTES);

    // K0: stats zero + dtype probe
    setup_kernel<<<1, 160>>>(ei, N);

    // K1: persistent per-node MLP (msg) + root transform (h)
    msg_kernel<<<nSM, MT, SMEM_BYTES>>>(x, W1, b1, W2, b2, Wr, br, N, numTiles);

    // K2: edge scatter (msg[src] -> h[dst])
    const long long units = (long long)E * 16;
    scatter_kernel<<<(int)((units + NT - 1) / NT), NT>>>(ei, E);

    // K3: PReLU + batch stats
    prelu_stats_kernel<<<592, NT>>>(pw, N);

    // K4: BN normalize -> out
    bn_kernel<<<592, NT>>>(out, gamma, beta, N);
}

// round 12
// speedup vs baseline: 1.6467x; 1.0334x over previous
#include <cuda_runtime.h>
#include <cstdint>

// ---------------------------------------------------------------------------
// GNBlock: h = BN(PReLU(segment_sum(relu(x[src]@W1+b1)@W2+b2, dst) + x@W_root + b_root))
// N=50000, E=800000, C_IN=64, C_HID=128, C_OUT=64
//
// setup -> persistent per-node MLP (msg,h) -> x4-MLP edge scatter (RED.v4)
// -> PReLU+stats (x2) -> BN (x2). No edge sort.
// ---------------------------------------------------------------------------

#define N_MAX 50000
#define C_IN 64
#define C_HID 128
#define C_OUT 64
#define TILE_N 128
#define MT 512
#define NT 256

__device__ __align__(16) float g_h[N_MAX * C_OUT];    // root -> h (post-PReLU)
__device__ __align__(16) float g_msg[N_MAX * C_OUT];  // per-node messages
__device__ float g_stats[2 * C_OUT];
__device__ int g_idx64;

// ---- f32x2 packed helpers ---------------------------------------------------
__device__ __forceinline__ unsigned long long pack2(float v) {
    unsigned long long r;
    unsigned int u = __float_as_uint(v);
    asm("mov.b64 %0, {%1, %2};" : "=l"(r) : "r"(u), "r"(u));
    return r;
}
__device__ __forceinline__ unsigned long long fma2(unsigned long long a,
                                                   unsigned long long b,
                                                   unsigned long long c) {
    unsigned long long d;
    asm("fma.rn.f32x2 %0, %1, %2, %3;" : "=l"(d) : "l"(a), "l"(b), "l"(c));
    return d;
}
__device__ __forceinline__ float2 unpack2(unsigned long long v) {
    unsigned int lo, hi;
    asm("mov.b64 {%0, %1}, %2;" : "=r"(lo), "=r"(hi) : "l"(v));
    float2 f;
    f.x = __uint_as_float(lo);
    f.y = __uint_as_float(hi);
    return f;
}

// ---------------------------------------------------------------------------
// K0: zero stats + detect index width
// ---------------------------------------------------------------------------
__global__ void setup_kernel(const void* __restrict__ ei, int N) {
    int tid = threadIdx.x;
    if (tid < 128) g_stats[tid] = 0.f;
    if (tid >= 128 && tid < 160) {
        const long long* p = (const long long*)ei;
        long long v = p[tid - 128];
        unsigned ok = __ballot_sync(0xffffffffu, v >= 0 && v < (long long)N);
        if (tid == 128) g_idx64 = (ok == 0xffffffffu) ? 1 : 0;
    }
}

// ---------------------------------------------------------------------------
// K1: PERSISTENT fused per-node kernel (weights staged once per block):
//   msg[n] = relu(x[n]@W1 + b1) @ W2 + b2  -> g_msg
//   h[n]   = x[n]@W_root + b_root          -> g_h
// ---------------------------------------------------------------------------
#define SX_PITCH 68
#define SH_PITCH 132
#define SMEM_FLOATS (8192 + 8192 + 4096 + TILE_N * SX_PITCH + TILE_N * SH_PITCH + 256)
#define SMEM_BYTES (SMEM_FLOATS * 4)

__global__ __launch_bounds__(MT) void msg_kernel(
    const float* __restrict__ x, const float* __restrict__ W1,
    const float* __restrict__ b1, const float* __restrict__ W2,
    const float* __restrict__ b2, const float* __restrict__ Wr,
    const float* __restrict__ br, int N, int numTiles) {
    extern __shared__ float sm[];
    float* sW1 = sm;                      // 64 x 128
    float* sW2 = sW1 + 64 * 128;          // 128 x 64
    float* sWr = sW2 + 128 * 64;          // 64 x 64
    float* sX = sWr + 64 * 64;            // 128 x 68 (padded)
    float* sH = sX + TILE_N * SX_PITCH;   // 128 x 132 (padded)
    float* sb1 = sH + TILE_N * SH_PITCH;  // 128
    float* sb2 = sb1 + 128;               // 64
    float* sbr = sb2 + 64;                // 64

    const int tid = threadIdx.x;

    for (int i = tid; i < 2048; i += MT)
        reinterpret_cast<float4*>(sW1)[i] = reinterpret_cast<const float4*>(W1)[i];
    for (int i = tid; i < 2048; i += MT)
        reinterpret_cast<float4*>(sW2)[i] = reinterpret_cast<const float4*>(W2)[i];
    for (int i = tid; i < 1024; i += MT)
        reinterpret_cast<float4*>(sWr)[i] = reinterpret_cast<const float4*>(Wr)[i];
    if (tid < 128) sb1[tid] = b1[tid];
    else if (tid < 192) sb2[tid - 128] = b2[tid - 128];
    else if (tid < 256) sbr[tid - 192] = br[tid - 192];

    const int hg = tid & 15;
    const int rg = tid >> 4;
    const int hb = hg * 8;
    const int kb = hg * 4;
    const int rb = rg * 4;

    for (int tile = blockIdx.x; tile < numTiles; tile += gridDim.x) {
        const int n0 = tile * TILE_N;
        __syncthreads();  // prior tile's sH readers done; weights staged

        for (int i = tid; i < TILE_N * 16; i += MT) {
            int r = i >> 4, q = i & 15;
            int n = n0 + r;
            if (n >= N) n = N - 1;
            float4 v = reinterpret_cast<const float4*>(x + (long long)n * C_IN)[q];
            *reinterpret_cast<float4*>(&sX[r * SX_PITCH + q * 4]) = v;
        }
        __syncthreads();

        // ---- GEMM1: sH = relu(sX @ W1 + b1) ----
        {
            unsigned long long acc[4][4];
#pragma unroll
            for (int e = 0; e < 4; e++)
#pragma unroll
                for (int p = 0; p < 4; p++) acc[e][p] = 0ULL;

#pragma unroll 8
            for (int k = 0; k < C_IN; k += 2) {
                ulonglong2 wa0 = *reinterpret_cast<const ulonglong2*>(&sW1[k * C_HID + hb]);
                ulonglong2 wa1 =
                    *reinterpret_cast<const ulonglong2*>(&sW1[k * C_HID + hb + 4]);
                ulonglong2 wb0 =
                    *reinterpret_cast<const ulonglong2*>(&sW1[(k + 1) * C_HID + hb]);
                ulonglong2 wb1 =
                    *reinterpret_cast<const ulonglong2*>(&sW1[(k + 1) * C_HID + hb + 4]);
#pragma unroll
                for (int e = 0; e < 4; e++) {
                    float2 xv = *reinterpret_cast<const float2*>(&sX[(rb + e) * SX_PITCH + k]);
                    unsigned long long x0 = pack2(xv.x), x1 = pack2(xv.y);
                    acc[e][0] = fma2(x0, wa0.x, acc[e][0]);
                    acc[e][1] = fma2(x0, wa0.y, acc[e][1]);
                    acc[e][2] = fma2(x0, wa1.x, acc[e][2]);
                    acc[e][3] = fma2(x0, wa1.y, acc[e][3]);
                    acc[e][0] = fma2(x1, wb0.x, acc[e][0]);
                    acc[e][1] = fma2(x1, wb0.y, acc[e][1]);
                    acc[e][2] = fma2(x1, wb1.x, acc[e][2]);
                    acc[e][3] = fma2(x1, wb1.y, acc[e][3]);
                }
            }
#pragma unroll
            for (int e = 0; e < 4; e++) {
#pragma unroll
                for (int p = 0; p < 4; p++) {
                    float2 v = unpack2(acc[e][p]);
                    v.x = fmaxf(v.x + sb1[hb + 2 * p], 0.f);
                    v.y = fmaxf(v.y + sb1[hb + 2 * p + 1], 0.f);
                    *reinterpret_cast<float2*>(&sH[(rb + e) * SH_PITCH + hb + 2 * p]) = v;
                }
            }
        }

        // ---- GEMM3: g_h = sX @ W_root + b_root ----
        {
            unsigned long long a3[4][2];
#pragma unroll
            for (int e = 0; e < 4; e++) { a3[e][0] = 0ULL; a3[e][1] = 0ULL; }

#pragma unroll 8
            for (int k = 0; k < C_IN; k += 2) {
                ulonglong2 wa = *reinterpret_cast<const ulonglong2*>(&sWr[k * C_OUT + kb]);
                ulonglong2 wb =
                    *reinterpret_cast<const ulonglong2*>(&sWr[(k + 1) * C_OUT + kb]);
#pragma unroll
                for (int e = 0; e < 4; e++) {
                    float2 xv = *reinterpret_cast<const float2*>(&sX[(rb + e) * SX_PITCH + k]);
                    unsigned long long x0 = pack2(xv.x), x1 = pack2(xv.y);
                    a3[e][0] = fma2(x0, wa.x, a3[e][0]);
                    a3[e][1] = fma2(x0, wa.y, a3[e][1]);
                    a3[e][0] = fma2(x1, wb.x, a3[e][0]);
                    a3[e][1] = fma2(x1, wb.y, a3[e][1]);
                }
            }
            float c0 = sbr[kb], c1 = sbr[kb + 1], c2 = sbr[kb + 2], c3 = sbr[kb + 3];
#pragma unroll
            for (int e = 0; e < 4; e++) {
                int n = n0 + rb + e;
                if (n >= N) continue;
                float2 v0 = unpack2(a3[e][0]);
                float2 v1 = unpack2(a3[e][1]);
                float4 r;
                r.x = v0.x + c0; r.y = v0.y + c1; r.z = v1.x + c2; r.w = v1.y + c3;
                *reinterpret_cast<float4*>(&g_h[(long long)n * C_OUT + kb]) = r;
            }
        }
        __syncthreads();

        // ---- GEMM2: g_msg = sH @ W2 + b2 ----
        {
            unsigned long long a2[4][2];
#pragma unroll
            for (int e = 0; e < 4; e++) { a2[e][0] = 0ULL; a2[e][1] = 0ULL; }

#pragma unroll 8
            for (int j = 0; j < C_HID; j += 2) {
                ulonglong2 wa = *reinterpret_cast<const ulonglong2*>(&sW2[j * C_OUT + kb]);
                ulonglong2 wb =
                    *reinterpret_cast<const ulonglong2*>(&sW2[(j + 1) * C_OUT + kb]);
#pragma unroll
                for (int e = 0; e < 4; e++) {
                    float2 hv = *reinterpret_cast<const float2*>(&sH[(rb + e) * SH_PITCH + j]);
                    unsigned long long h0 = pack2(hv.x), h1 = pack2(hv.y);
                    a2[e][0] = fma2(h0, wa.x, a2[e][0]);
                    a2[e][1] = fma2(h0, wa.y, a2[e][1]);
                    a2[e][0] = fma2(h1, wb.x, a2[e][0]);
                    a2[e][1] = fma2(h1, wb.y, a2[e][1]);
                }
            }
            float c0 = sb2[kb], c1 = sb2[kb + 1], c2 = sb2[kb + 2], c3 = sb2[kb + 3];
#pragma unroll
            for (int e = 0; e < 4; e++) {
                int n = n0 + rb + e;
                if (n >= N) continue;
                float2 v0 = unpack2(a2[e][0]);
                float2 v1 = unpack2(a2[e][1]);
                float4 r;
                r.x = v0.x + c0; r.y = v0.y + c1; r.z = v1.x + c2; r.w = v1.y + c3;
                *reinterpret_cast<float4*>(&g_msg[(long long)n * C_OUT + kb]) = r;
            }
        }
    }
}

// ---------------------------------------------------------------------------
// K2: scatter  g_h[dst] += g_msg[src].  16 threads per edge-slot; each slot
// handles 4 edges at stride G=ceil(E/4) -> 4 independent idx->msg->RED chains
// in distinct registers (MLP=4). RED has no return value, so nothing blocks.
// ---------------------------------------------------------------------------
__global__ __launch_bounds__(NT) void scatter_kernel(const void* __restrict__ ei_raw,
                                                     int E, int G) {
    long long idx = (long long)blockIdx.x * NT + threadIdx.x;
    int base = (int)(idx >> 4);  // slot in [0, G)
    int q = (int)(idx & 15);
    if (base >= G) return;

    const int idx64 = g_idx64;
    int e0 = base, e1 = base + G, e2 = base + 2 * G, e3 = base + 3 * G;
    bool v1 = e1 < E, v2 = e2 < E, v3 = e3 < E;  // e0 < E always (G*4 >= E, base < G, e0=base<G<=E... guard anyway)
    bool v0 = e0 < E;

    int s0 = 0, d0 = 0, s1 = 0, d1 = 0, s2 = 0, d2 = 0, s3 = 0, d3 = 0;
    if (idx64) {
        const long long* p = (const long long*)ei_raw;
        if (v0) { s0 = (int)__ldg(&p[e0]); d0 = (int)__ldg(&p[E + e0]); }
        if (v1) { s1 = (int)__ldg(&p[e1]); d1 = (int)__ldg(&p[E + e1]); }
        if (v2) { s2 = (int)__ldg(&p[e2]); d2 = (int)__ldg(&p[E + e2]); }
        if (v3) { s3 = (int)__ldg(&p[e3]); d3 = (int)__ldg(&p[E + e3]); }
    } else {
        const int* p = (const int*)ei_raw;
        if (v0) { s0 = __ldg(&p[e0]); d0 = __ldg(&p[E + e0]); }
        if (v1) { s1 = __ldg(&p[e1]); d1 = __ldg(&p[E + e1]); }
        if (v2) { s2 = __ldg(&p[e2]); d2 = __ldg(&p[E + e2]); }
        if (v3) { s3 = __ldg(&p[e3]); d3 = __ldg(&p[E + e3]); }
    }

    float4 m0, m1, m2, m3;
    if (v0) m0 = *reinterpret_cast<const float4*>(&g_msg[(long long)s0 * C_OUT + q * 4]);
    if (v1) m1 = *reinterpret_cast<const float4*>(&g_msg[(long long)s1 * C_OUT + q * 4]);
    if (v2) m2 = *reinterpret_cast<const float4*>(&g_msg[(long long)s2 * C_OUT + q * 4]);
    if (v3) m3 = *reinterpret_cast<const float4*>(&g_msg[(long long)s3 * C_OUT + q * 4]);

    if (v0) {
        float* pd = &g_h[(long long)d0 * C_OUT + q * 4];
        asm volatile("red.global.add.v4.f32 [%0], {%1,%2,%3,%4};"
                     :: "l"(pd), "f"(m0.x), "f"(m0.y), "f"(m0.z), "f"(m0.w) : "memory");
    }
    if (v1) {
        float* pd = &g_h[(long long)d1 * C_OUT + q * 4];
        asm volatile("red.global.add.v4.f32 [%0], {%1,%2,%3,%4};"
                     :: "l"(pd), "f"(m1.x), "f"(m1.y), "f"(m1.z), "f"(m1.w) : "memory");
    }
    if (v2) {
        float* pd = &g_h[(long long)d2 * C_OUT + q * 4];
        asm volatile("red.global.add.v4.f32 [%0], {%1,%2,%3,%4};"
                     :: "l"(pd), "f"(m2.x), "f"(m2.y), "f"(m2.z), "f"(m2.w) : "memory");
    }
    if (v3) {
        float* pd = &g_h[(long long)d3 * C_OUT + q * 4];
        asm volatile("red.global.add.v4.f32 [%0], {%1,%2,%3,%4};"
                     :: "l"(pd), "f"(m3.x), "f"(m3.y), "f"(m3.z), "f"(m3.w) : "memory");
    }
}

// ---------------------------------------------------------------------------
// K3: PReLU in-place (float4, x2 independent streams) + per-channel stats.
// Second stream offset is a multiple of 16 float4s -> same channel quad.
// ---------------------------------------------------------------------------
__global__ void prelu_stats_kernel(const float* __restrict__ prelu_w, int N) {
    const float a = prelu_w[0];
    const int total4 = N * (C_OUT / 4);
    const int half4 = ((total4 / 2) + 15) & ~15;  // multiple of 16
    const int stride = gridDim.x * blockDim.x;
    float4* gh4 = reinterpret_cast<float4*>(g_h);
    float s0 = 0.f, s1 = 0.f, s2 = 0.f, s3 = 0.f;
    float q0 = 0.f, q1 = 0.f, q2 = 0.f, q3 = 0.f;
    for (int i = blockIdx.x * blockDim.x + threadIdx.x; i < half4; i += stride) {
        float4 v = gh4[i];
        int j = i + half4;
        bool jv = j < total4;
        float4 w;
        if (jv) w = gh4[j];
        v.x = (v.x >= 0.f) ? v.x : a * v.x;
        v.y = (v.y >= 0.f) ? v.y : a * v.y;
        v.z = (v.z >= 0.f) ? v.z : a * v.z;
        v.w = (v.w >= 0.f) ? v.w : a * v.w;
        gh4[i] = v;
        s0 += v.x; s1 += v.y; s2 += v.z; s3 += v.w;
        q0 += v.x * v.x; q1 += v.y * v.y; q2 += v.z * v.z; q3 += v.w * v.w;
        if (jv) {
            w.x = (w.x >= 0.f) ? w.x : a * w.x;
            w.y = (w.y >= 0.f) ? w.y : a * w.y;
            w.z = (w.z >= 0.f) ? w.z : a * w.z;
            w.w = (w.w >= 0.f) ? w.w : a * w.w;
            gh4[j] = w;
            s0 += w.x; s1 += w.y; s2 += w.z; s3 += w.w;
            q0 += w.x * w.x; q1 += w.y * w.y; q2 += w.z * w.z; q3 += w.w * w.w;
        }
    }
    __shared__ float rs[NT * 4], rq[NT * 4];
    int t = threadIdx.x;
    rs[t * 4 + 0] = s0; rs[t * 4 + 1] = s1; rs[t * 4 + 2] = s2; rs[t * 4 + 3] = s3;
    rq[t * 4 + 0] = q0; rq[t * 4 + 1] = q1; rq[t * 4 + 2] = q2; rq[t * 4 + 3] = q3;
    __syncthreads();
    if (t < 64) {
        int qq = t >> 2, comp = t & 3;
        float ts = 0.f, tq = 0.f;
#pragma unroll
        for (int m = 0; m < 16; m++) {
            int src = (m * 16 + qq) * 4 + comp;
            ts += rs[src];
            tq += rq[src];
        }
        atomicAdd(&g_stats[t], ts);
        atomicAdd(&g_stats[64 + t], tq);
    }
}

// ---------------------------------------------------------------------------
// K4: finalize BN (g_h already PReLU'd) -> out, x2 independent streams
// ---------------------------------------------------------------------------
__global__ void bn_kernel(float* __restrict__ out, const float* __restrict__ gamma,
                          const float* __restrict__ beta, int N) {
    __shared__ float sscale[C_OUT], sshift[C_OUT];
    if (threadIdx.x < C_OUT) {
        float invN = 1.f / (float)N;
        float mu = g_stats[threadIdx.x] * invN;
        float var = g_stats[64 + threadIdx.x] * invN - mu * mu;
        float inv = rsqrtf(var + 1e-5f);
        float g = gamma[threadIdx.x] * inv;
        sscale[threadIdx.x] = g;
        sshift[threadIdx.x] = beta[threadIdx.x] - mu * g;
    }
    __syncthreads();
    const int total4 = N * (C_OUT / 4);
    const int half4 = ((total4 / 2) + 15) & ~15;
    const int stride = gridDim.x * blockDim.x;
    const float4* gh4 = reinterpret_cast<const float4*>(g_h);
    float4* o4 = reinterpret_cast<float4*>(out);
    for (int i = blockIdx.x * blockDim.x + threadIdx.x; i < half4; i += stride) {
        int q = (i & 15);
        float4 sc = reinterpret_cast<const float4*>(sscale)[q];
        float4 sh = reinterpret_cast<const float4*>(sshift)[q];
        float4 v = gh4[i];
        int j = i + half4;
        bool jv = j < total4;
        float4 w;
        if (jv) w = gh4[j];
        float4 r;
        r.x = fmaf(v.x, sc.x, sh.x);
        r.y = fmaf(v.y, sc.y, sh.y);
        r.z = fmaf(v.z, sc.z, sh.z);
        r.w = fmaf(v.w, sc.w, sh.w);
        o4[i] = r;
        if (jv) {
            float4 r2;
            r2.x = fmaf(w.x, sc.x, sh.x);
            r2.y = fmaf(w.y, sc.y, sh.y);
            r2.z = fmaf(w.z, sc.z, sh.z);
            r2.w = fmaf(w.w, sc.w, sh.w);
            o4[j] = r2;
        }
    }
}

// ---------------------------------------------------------------------------
extern "C" void kernel_launch(void* const* d_in, const int* in_sizes, int n_in,
                              void* d_out, int out_size) {
    const float* x = (const float*)d_in[0];
    const void* ei = d_in[1];
    const float* W1 = (const float*)d_in[2];
    const float* b1 = (const float*)d_in[3];
    const float* W2 = (const float*)d_in[4];
    const float* b2 = (const float*)d_in[5];
    const float* Wr = (const float*)d_in[6];
    const float* br = (const float*)d_in[7];
    const float* pw = (const float*)d_in[8];
    const float* gamma = (const float*)d_in[9];
    const float* beta = (const float*)d_in[10];
    float* out = (float*)d_out;

    const int N = in_sizes[0] / C_IN;
    const int E = in_sizes[1] / 2;
    const int numTiles = (N + TILE_N - 1) / TILE_N;
    const int G = (E + 3) / 4;  // edges per scatter wave

    static int nSM = 0;
    if (nSM == 0) cudaDeviceGetAttribute(&nSM, cudaDevAttrMultiProcessorCount, 0);

    cudaFuncSetAttribute(msg_kernel, cudaFuncAttributeMaxDynamicSharedMemorySize,
                         SMEM_BYTES);

    // K0: stats zero + dtype probe
    setup_kernel<<<1, 160>>>(ei, N);

    // K1: persistent per-node MLP (msg) + root transform (h)
    msg_kernel<<<nSM, MT, SMEM_BYTES>>>(x, W1, b1, W2, b2, Wr, br, N, numTiles);

    // K2: edge scatter, 4 edges per 16-thread slot (MLP=4)
    const long long units = (long long)G * 16;
    scatter_kernel<<<(int)((units + NT - 1) / NT), NT>>>(ei, E, G);

    // K3: PReLU + batch stats (x2)
    prelu_stats_kernel<<<592, NT>>>(pw, N);

    // K4: BN normalize -> out (x2)
    bn_kernel<<<592, NT>>>(out, gamma, beta, N);
}

// round 13
// speedup vs baseline: 1.7239x; 1.0469x over previous
#include <cuda_runtime.h>
#include <cstdint>

// ---------------------------------------------------------------------------
// GNBlock: h = BN(PReLU(segment_sum(relu(x[src]@W1+b1)@W2+b2, dst) + x@W_root + b_root))
// N=50000, E=800000, C_IN=64, C_HID=128, C_OUT=64
//
// msg (persistent, double-buffered X pipeline, setup folded into block 0)
// -> x4-MLP edge scatter (RED.v4) -> read-only PReLU stats -> BN(+PReLU) out.
// 4 launches.
// ---------------------------------------------------------------------------

#define N_MAX 50000
#define C_IN 64
#define C_HID 128
#define C_OUT 64
#define TILE_N 128
#define MT 512
#define NT 256

__device__ __align__(16) float g_h[N_MAX * C_OUT];    // root transform (pre-PReLU)
__device__ __align__(16) float g_msg[N_MAX * C_OUT];  // per-node messages
__device__ float g_stats[2 * C_OUT];
__device__ int g_idx64;

// ---- f32x2 packed helpers ---------------------------------------------------
__device__ __forceinline__ unsigned long long pack2(float v) {
    unsigned long long r;
    unsigned int u = __float_as_uint(v);
    asm("mov.b64 %0, {%1, %2};" : "=l"(r) : "r"(u), "r"(u));
    return r;
}
__device__ __forceinline__ unsigned long long fma2(unsigned long long a,
                                                   unsigned long long b,
                                                   unsigned long long c) {
    unsigned long long d;
    asm("fma.rn.f32x2 %0, %1, %2, %3;" : "=l"(d) : "l"(a), "l"(b), "l"(c));
    return d;
}
__device__ __forceinline__ float2 unpack2(unsigned long long v) {
    unsigned int lo, hi;
    asm("mov.b64 {%0, %1}, %2;" : "=r"(lo), "=r"(hi) : "l"(v));
    float2 f;
    f.x = __uint_as_float(lo);
    f.y = __uint_as_float(hi);
    return f;
}

// ---------------------------------------------------------------------------
// K1: PERSISTENT fused per-node kernel.
//   block 0 also zeroes g_stats and probes index dtype (setup folded in).
//   Double-buffered X staging: prefetch(tile+grid) overlaps GEMM1+GEMM3.
//   msg[n] = relu(x[n]@W1 + b1) @ W2 + b2  -> g_msg
//   h[n]   = x[n]@W_root + b_root          -> g_h
// ---------------------------------------------------------------------------
#define SX_PITCH 68
#define SH_PITCH 132
#define XBUF (TILE_N * SX_PITCH)
#define SMEM_FLOATS (8192 + 8192 + 4096 + 2 * XBUF + TILE_N * SH_PITCH + 256)
#define SMEM_BYTES (SMEM_FLOATS * 4)

__global__ __launch_bounds__(MT) void msg_kernel(
    const float* __restrict__ x, const float* __restrict__ W1,
    const float* __restrict__ b1, const float* __restrict__ W2,
    const float* __restrict__ b2, const float* __restrict__ Wr,
    const float* __restrict__ br, const void* __restrict__ ei, int N,
    int numTiles) {
    extern __shared__ float sm[];
    float* sW1 = sm;                       // 64 x 128
    float* sW2 = sW1 + 64 * 128;           // 128 x 64
    float* sWr = sW2 + 128 * 64;           // 64 x 64
    float* sX0 = sWr + 64 * 64;            // 2 x (128 x 68)
    float* sH = sX0 + 2 * XBUF;            // 128 x 132
    float* sb1 = sH + TILE_N * SH_PITCH;   // 128
    float* sb2 = sb1 + 128;                // 64
    float* sbr = sb2 + 64;                 // 64

    const int tid = threadIdx.x;

    // folded setup (block 0): zero stats + dtype probe
    if (blockIdx.x == 0) {
        if (tid < 128) g_stats[tid] = 0.f;
        if (tid >= 128 && tid < 160) {
            const long long* p = (const long long*)ei;
            long long v = p[tid - 128];
            unsigned ok = __ballot_sync(0xffffffffu, v >= 0 && v < (long long)N);
            if (tid == 128) g_idx64 = (ok == 0xffffffffu) ? 1 : 0;
        }
    }

    // stage weights + biases once
    for (int i = tid; i < 2048; i += MT)
        reinterpret_cast<float4*>(sW1)[i] = reinterpret_cast<const float4*>(W1)[i];
    for (int i = tid; i < 2048; i += MT)
        reinterpret_cast<float4*>(sW2)[i] = reinterpret_cast<const float4*>(W2)[i];
    for (int i = tid; i < 1024; i += MT)
        reinterpret_cast<float4*>(sWr)[i] = reinterpret_cast<const float4*>(Wr)[i];
    if (tid < 128) sb1[tid] = b1[tid];
    else if (tid < 192) sb2[tid - 128] = b2[tid - 128];
    else if (tid < 256) sbr[tid - 192] = br[tid - 192];

    const int hg = tid & 15;
    const int rg = tid >> 4;
    const int hb = hg * 8;
    const int kb = hg * 4;
    const int rb = rg * 4;

    int tile = blockIdx.x;
    int bufIdx = 0;

    // stage first tile
    if (tile < numTiles) {
#pragma unroll
        for (int j = 0; j < 4; j++) {
            int i = j * MT + tid;
            int r = i >> 4, q = i & 15;
            int n = tile * TILE_N + r;
            if (n >= N) n = N - 1;
            float4 v = reinterpret_cast<const float4*>(x + (long long)n * C_IN)[q];
            *reinterpret_cast<float4*>(&sX0[r * SX_PITCH + q * 4]) = v;
        }
    }
    __syncthreads();

    for (; tile < numTiles; tile += gridDim.x, bufIdx ^= 1) {
        const int n0 = tile * TILE_N;
        float* sXc = sX0 + bufIdx * XBUF;
        float* sXn = sX0 + (bufIdx ^ 1) * XBUF;
        const int next = tile + gridDim.x;

        // issue prefetch loads for the next tile (hidden behind GEMM1/GEMM3)
        float4 pf[4];
        if (next < numTiles) {
#pragma unroll
            for (int j = 0; j < 4; j++) {
                int i = j * MT + tid;
                int r = i >> 4, q = i & 15;
                int n = next * TILE_N + r;
                if (n >= N) n = N - 1;
                pf[j] = __ldg(&reinterpret_cast<const float4*>(x + (long long)n * C_IN)[q]);
            }
        }

        // ---- GEMM1: sH = relu(sXc @ W1 + b1) ----
        {
            unsigned long long acc[4][4];
#pragma unroll
            for (int e = 0; e < 4; e++)
#pragma unroll
                for (int p = 0; p < 4; p++) acc[e][p] = 0ULL;

#pragma unroll 8
            for (int k = 0; k < C_IN; k += 2) {
                ulonglong2 wa0 = *reinterpret_cast<const ulonglong2*>(&sW1[k * C_HID + hb]);
                ulonglong2 wa1 =
                    *reinterpret_cast<const ulonglong2*>(&sW1[k * C_HID + hb + 4]);
                ulonglong2 wb0 =
                    *reinterpret_cast<const ulonglong2*>(&sW1[(k + 1) * C_HID + hb]);
                ulonglong2 wb1 =
                    *reinterpret_cast<const ulonglong2*>(&sW1[(k + 1) * C_HID + hb + 4]);
#pragma unroll
                for (int e = 0; e < 4; e++) {
                    float2 xv = *reinterpret_cast<const float2*>(&sXc[(rb + e) * SX_PITCH + k]);
                    unsigned long long x0 = pack2(xv.x), x1 = pack2(xv.y);
                    acc[e][0] = fma2(x0, wa0.x, acc[e][0]);
                    acc[e][1] = fma2(x0, wa0.y, acc[e][1]);
                    acc[e][2] = fma2(x0, wa1.x, acc[e][2]);
                    acc[e][3] = fma2(x0, wa1.y, acc[e][3]);
                    acc[e][0] = fma2(x1, wb0.x, acc[e][0]);
                    acc[e][1] = fma2(x1, wb0.y, acc[e][1]);
                    acc[e][2] = fma2(x1, wb1.x, acc[e][2]);
                    acc[e][3] = fma2(x1, wb1.y, acc[e][3]);
                }
            }
#pragma unroll
            for (int e = 0; e < 4; e++) {
#pragma unroll
                for (int p = 0; p < 4; p++) {
                    float2 v = unpack2(acc[e][p]);
                    v.x = fmaxf(v.x + sb1[hb + 2 * p], 0.f);
                    v.y = fmaxf(v.y + sb1[hb + 2 * p + 1], 0.f);
                    *reinterpret_cast<float2*>(&sH[(rb + e) * SH_PITCH + hb + 2 * p]) = v;
                }
            }
        }

        // ---- GEMM3: g_h = sXc @ W_root + b_root ----
        {
            unsigned long long a3[4][2];
#pragma unroll
            for (int e = 0; e < 4; e++) { a3[e][0] = 0ULL; a3[e][1] = 0ULL; }

#pragma unroll 8
            for (int k = 0; k < C_IN; k += 2) {
                ulonglong2 wa = *reinterpret_cast<const ulonglong2*>(&sWr[k * C_OUT + kb]);
                ulonglong2 wb =
                    *reinterpret_cast<const ulonglong2*>(&sWr[(k + 1) * C_OUT + kb]);
#pragma unroll
                for (int e = 0; e < 4; e++) {
                    float2 xv = *reinterpret_cast<const float2*>(&sXc[(rb + e) * SX_PITCH + k]);
                    unsigned long long x0 = pack2(xv.x), x1 = pack2(xv.y);
                    a3[e][0] = fma2(x0, wa.x, a3[e][0]);
                    a3[e][1] = fma2(x0, wa.y, a3[e][1]);
                    a3[e][0] = fma2(x1, wb.x, a3[e][0]);
                    a3[e][1] = fma2(x1, wb.y, a3[e][1]);
                }
            }
            float c0 = sbr[kb], c1 = sbr[kb + 1], c2 = sbr[kb + 2], c3 = sbr[kb + 3];
#pragma unroll
            for (int e = 0; e < 4; e++) {
                int n = n0 + rb + e;
                if (n >= N) continue;
                float2 v0 = unpack2(a3[e][0]);
                float2 v1 = unpack2(a3[e][1]);
                float4 r;
                r.x = v0.x + c0; r.y = v0.y + c1; r.z = v1.x + c2; r.w = v1.y + c3;
                *reinterpret_cast<float4*>(&g_h[(long long)n * C_OUT + kb]) = r;
            }
        }

        // store prefetched X into the other buffer
        if (next < numTiles) {
#pragma unroll
            for (int j = 0; j < 4; j++) {
                int i = j * MT + tid;
                int r = i >> 4, q = i & 15;
                *reinterpret_cast<float4*>(&sXn[r * SX_PITCH + q * 4]) = pf[j];
            }
        }
        __syncthreads();  // sH complete; next-X staged

        // ---- GEMM2: g_msg = sH @ W2 + b2 ----
        {
            unsigned long long a2[4][2];
#pragma unroll
            for (int e = 0; e < 4; e++) { a2[e][0] = 0ULL; a2[e][1] = 0ULL; }

#pragma unroll 8
            for (int j = 0; j < C_HID; j += 2) {
                ulonglong2 wa = *reinterpret_cast<const ulonglong2*>(&sW2[j * C_OUT + kb]);
                ulonglong2 wb =
                    *reinterpret_cast<const ulonglong2*>(&sW2[(j + 1) * C_OUT + kb]);
#pragma unroll
                for (int e = 0; e < 4; e++) {
                    float2 hv = *reinterpret_cast<const float2*>(&sH[(rb + e) * SH_PITCH + j]);
                    unsigned long long h0 = pack2(hv.x), h1 = pack2(hv.y);
                    a2[e][0] = fma2(h0, wa.x, a2[e][0]);
                    a2[e][1] = fma2(h0, wa.y, a2[e][1]);
                    a2[e][0] = fma2(h1, wb.x, a2[e][0]);
                    a2[e][1] = fma2(h1, wb.y, a2[e][1]);
                }
            }
            float c0 = sb2[kb], c1 = sb2[kb + 1], c2 = sb2[kb + 2], c3 = sb2[kb + 3];
#pragma unroll
            for (int e = 0; e < 4; e++) {
                int n = n0 + rb + e;
                if (n >= N) continue;
                float2 v0 = unpack2(a2[e][0]);
                float2 v1 = unpack2(a2[e][1]);
                float4 r;
                r.x = v0.x + c0; r.y = v0.y + c1; r.z = v1.x + c2; r.w = v1.y + c3;
                *reinterpret_cast<float4*>(&g_msg[(long long)n * C_OUT + kb]) = r;
            }
        }
        __syncthreads();  // GEMM2's sH reads done before next GEMM1 writes sH
    }
}

// ---------------------------------------------------------------------------
// K2: scatter  g_h[dst] += g_msg[src].  16 threads per edge-slot; each slot
// handles 4 edges at stride G -> 4 independent idx->msg->RED chains (MLP=4).
// ---------------------------------------------------------------------------
__global__ __launch_bounds__(NT) void scatter_kernel(const void* __restrict__ ei_raw,
                                                     int E, int G) {
    long long idx = (long long)blockIdx.x * NT + threadIdx.x;
    int base = (int)(idx >> 4);
    int q = (int)(idx & 15);
    if (base >= G) return;

    const int idx64 = g_idx64;
    int e0 = base, e1 = base + G, e2 = base + 2 * G, e3 = base + 3 * G;
    bool v0 = e0 < E, v1 = e1 < E, v2 = e2 < E, v3 = e3 < E;

    int s0 = 0, d0 = 0, s1 = 0, d1 = 0, s2 = 0, d2 = 0, s3 = 0, d3 = 0;
    if (idx64) {
        const long long* p = (const long long*)ei_raw;
        if (v0) { s0 = (int)__ldg(&p[e0]); d0 = (int)__ldg(&p[E + e0]); }
        if (v1) { s1 = (int)__ldg(&p[e1]); d1 = (int)__ldg(&p[E + e1]); }
        if (v2) { s2 = (int)__ldg(&p[e2]); d2 = (int)__ldg(&p[E + e2]); }
        if (v3) { s3 = (int)__ldg(&p[e3]); d3 = (int)__ldg(&p[E + e3]); }
    } else {
        const int* p = (const int*)ei_raw;
        if (v0) { s0 = __ldg(&p[e0]); d0 = __ldg(&p[E + e0]); }
        if (v1) { s1 = __ldg(&p[e1]); d1 = __ldg(&p[E + e1]); }
        if (v2) { s2 = __ldg(&p[e2]); d2 = __ldg(&p[E + e2]); }
        if (v3) { s3 = __ldg(&p[e3]); d3 = __ldg(&p[E + e3]); }
    }

    float4 m0, m1, m2, m3;
    if (v0) m0 = *reinterpret_cast<const float4*>(&g_msg[(long long)s0 * C_OUT + q * 4]);
    if (v1) m1 = *reinterpret_cast<const float4*>(&g_msg[(long long)s1 * C_OUT + q * 4]);
    if (v2) m2 = *reinterpret_cast<const float4*>(&g_msg[(long long)s2 * C_OUT + q * 4]);
    if (v3) m3 = *reinterpret_cast<const float4*>(&g_msg[(long long)s3 * C_OUT + q * 4]);

    if (v0) {
        float* pd = &g_h[(long long)d0 * C_OUT + q * 4];
        asm volatile("red.global.add.v4.f32 [%0], {%1,%2,%3,%4};"
                     :: "l"(pd), "f"(m0.x), "f"(m0.y), "f"(m0.z), "f"(m0.w) : "memory");
    }
    if (v1) {
        float* pd = &g_h[(long long)d1 * C_OUT + q * 4];
        asm volatile("red.global.add.v4.f32 [%0], {%1,%2,%3,%4};"
                     :: "l"(pd), "f"(m1.x), "f"(m1.y), "f"(m1.z), "f"(m1.w) : "memory");
    }
    if (v2) {
        float* pd = &g_h[(long long)d2 * C_OUT + q * 4];
        asm volatile("red.global.add.v4.f32 [%0], {%1,%2,%3,%4};"
                     :: "l"(pd), "f"(m2.x), "f"(m2.y), "f"(m2.z), "f"(m2.w) : "memory");
    }
    if (v3) {
        float* pd = &g_h[(long long)d3 * C_OUT + q * 4];
        asm volatile("red.global.add.v4.f32 [%0], {%1,%2,%3,%4};"
                     :: "l"(pd), "f"(m3.x), "f"(m3.y), "f"(m3.z), "f"(m3.w) : "memory");
    }
}

// ---------------------------------------------------------------------------
// K3: READ-ONLY stats pass: per-channel sum/sumsq of PReLU(g_h).
// (PReLU not stored; bn recomputes it — saves the 12.8MB write-back.)
// ---------------------------------------------------------------------------
__global__ void prelu_stats_kernel(const float* __restrict__ prelu_w, int N) {
    const float a = prelu_w[0];
    const int total4 = N * (C_OUT / 4);
    const int stride = gridDim.x * blockDim.x;
    const float4* gh4 = reinterpret_cast<const float4*>(g_h);
    float s0 = 0.f, s1 = 0.f, s2 = 0.f, s3 = 0.f;
    float q0 = 0.f, q1 = 0.f, q2 = 0.f, q3 = 0.f;
    // stride multiple of 16 -> fixed channel quad per thread
    for (int i = blockIdx.x * blockDim.x + threadIdx.x; i < total4; i += stride) {
        float4 v = gh4[i];
        v.x = (v.x >= 0.f) ? v.x : a * v.x;
        v.y = (v.y >= 0.f) ? v.y : a * v.y;
        v.z = (v.z >= 0.f) ? v.z : a * v.z;
        v.w = (v.w >= 0.f) ? v.w : a * v.w;
        s0 += v.x; s1 += v.y; s2 += v.z; s3 += v.w;
        q0 += v.x * v.x; q1 += v.y * v.y; q2 += v.z * v.z; q3 += v.w * v.w;
    }
    __shared__ float rs[NT * 4], rq[NT * 4];
    int t = threadIdx.x;
    rs[t * 4 + 0] = s0; rs[t * 4 + 1] = s1; rs[t * 4 + 2] = s2; rs[t * 4 + 3] = s3;
    rq[t * 4 + 0] = q0; rq[t * 4 + 1] = q1; rq[t * 4 + 2] = q2; rq[t * 4 + 3] = q3;
    __syncthreads();
    if (t < 64) {
        int qq = t >> 2, comp = t & 3;
        float ts = 0.f, tq = 0.f;
#pragma unroll
        for (int m = 0; m < 16; m++) {
            int src = (m * 16 + qq) * 4 + comp;
            ts += rs[src];
            tq += rq[src];
        }
        atomicAdd(&g_stats[t], ts);
        atomicAdd(&g_stats[64 + t], tq);
    }
}

// ---------------------------------------------------------------------------
// K4: finalize — recompute PReLU, normalize, write out
// ---------------------------------------------------------------------------
__global__ void bn_kernel(float* __restrict__ out, const float* __restrict__ gamma,
                          const float* __restrict__ beta,
                          const float* __restrict__ prelu_w, int N) {
    __shared__ float sscale[C_OUT], sshift[C_OUT];
    if (threadIdx.x < C_OUT) {
        float invN = 1.f / (float)N;
        float mu = g_stats[threadIdx.x] * invN;
        float var = g_stats[64 + threadIdx.x] * invN - mu * mu;
        float inv = rsqrtf(var + 1e-5f);
        float g = gamma[threadIdx.x] * inv;
        sscale[threadIdx.x] = g;
        sshift[threadIdx.x] = beta[threadIdx.x] - mu * g;
    }
    __syncthreads();
    const float a = prelu_w[0];
    const int total4 = N * (C_OUT / 4);
    const int stride = gridDim.x * blockDim.x;
    const float4* gh4 = reinterpret_cast<const float4*>(g_h);
    float4* o4 = reinterpret_cast<float4*>(out);
    for (int i = blockIdx.x * blockDim.x + threadIdx.x; i < total4; i += stride) {
        int q = (i & 15);
        float4 sc = reinterpret_cast<const float4*>(sscale)[q];
        float4 sh = reinterpret_cast<const float4*>(sshift)[q];
        float4 v = gh4[i];
        v.x = (v.x >= 0.f) ? v.x : a * v.x;
        v.y = (v.y >= 0.f) ? v.y : a * v.y;
        v.z = (v.z >= 0.f) ? v.z : a * v.z;
        v.w = (v.w >= 0.f) ? v.w : a * v.w;
        float4 r;
        r.x = fmaf(v.x, sc.x, sh.x);
        r.y = fmaf(v.y, sc.y, sh.y);
        r.z = fmaf(v.z, sc.z, sh.z);
        r.w = fmaf(v.w, sc.w, sh.w);
        o4[i] = r;
    }
}

// ---------------------------------------------------------------------------
extern "C" void kernel_launch(void* const* d_in, const int* in_sizes, int n_in,
                              void* d_out, int out_size) {
    const float* x = (const float*)d_in[0];
    const void* ei = d_in[1];
    const float* W1 = (const float*)d_in[2];
    const float* b1 = (const float*)d_in[3];
    const float* W2 = (const float*)d_in[4];
    const float* b2 = (const float*)d_in[5];
    const float* Wr = (const float*)d_in[6];
    const float* br = (const float*)d_in[7];
    const float* pw = (const float*)d_in[8];
    const float* gamma = (const float*)d_in[9];
    const float* beta = (const float*)d_in[10];
    float* out = (float*)d_out;

    const int N = in_sizes[0] / C_IN;
    const int E = in_sizes[1] / 2;
    const int numTiles = (N + TILE_N - 1) / TILE_N;
    const int G = (E + 3) / 4;

    static int nSM = 0;
    if (nSM == 0) cudaDeviceGetAttribute(&nSM, cudaDevAttrMultiProcessorCount, 0);

    cudaFuncSetAttribute(msg_kernel, cudaFuncAttributeMaxDynamicSharedMemorySize,
                         SMEM_BYTES);

    // K1: persistent per-node MLP + root transform (setup folded into block 0)
    msg_kernel<<<nSM, MT, SMEM_BYTES>>>(x, W1, b1, W2, b2, Wr, br, ei, N, numTiles);

    // K2: edge scatter, 4 edges per 16-thread slot
    const long long units = (long long)G * 16;
    scatter_kernel<<<(int)((units + NT - 1) / NT), NT>>>(ei, E, G);

    // K3: stats (read-only)
    prelu_stats_kernel<<<592, NT>>>(pw, N);

    // K4: PReLU + BN normalize -> out
    bn_kernel<<<592, NT>>>(out, gamma, beta, pw, N);
}